// round 2
// baseline (speedup 1.0000x reference)
#include <cuda_runtime.h>
#include <math.h>

#define D_MODEL 1024
#define NH      16
#define DKH     64
#define D_FF    4096
#define BATCH   4
#define SEQ     2048
#define NROWS   (BATCH*SEQ)

// ---------------- scratch (device globals; no runtime allocation) ----------
__device__ float g_xn[NROWS * D_MODEL];
__device__ float g_q [NROWS * D_MODEL];
__device__ float g_k [NROWS * D_MODEL];
__device__ float g_v [NROWS * D_MODEL];
__device__ float g_ao[NROWS * D_MODEL];
__device__ float g_x1[NROWS * D_MODEL];
__device__ float g_h [NROWS * D_MODEL];
__device__ float g_ff[(size_t)NROWS * D_FF];
__device__ float g_x2[NROWS * D_MODEL];

// ---------------- packed fp32x2 FMA (sm_100+ PTX only) ---------------------
__device__ __forceinline__ void ffma2(float2& d, float2 a, float2 b) {
    asm("fma.rn.f32x2 %0, %1, %2, %0;"
        : "+l"(reinterpret_cast<unsigned long long&>(d))
        : "l"(reinterpret_cast<unsigned long long&>(a)),
          "l"(reinterpret_cast<unsigned long long&>(b)));
}

// ---------------- layernorm (unbiased std, no eps) --------------------------
__device__ __forceinline__ float block_sum(float v, float* red) {
    __syncthreads();                       // protect red reuse
    #pragma unroll
    for (int o = 16; o; o >>= 1) v += __shfl_xor_sync(0xffffffffu, v, o);
    int tid = threadIdx.x;
    if ((tid & 31) == 0) red[tid >> 5] = v;
    __syncthreads();
    if (tid == 0) {
        float t = 0.f;
        #pragma unroll
        for (int i = 0; i < 8; i++) t += red[i];
        red[0] = t;
    }
    __syncthreads();
    return red[0];
}

__global__ __launch_bounds__(256) void ln_kernel(
    const float* __restrict__ x, const float* __restrict__ ga,
    const float* __restrict__ gb, float* __restrict__ out)
{
    __shared__ float red[8];
    const int row = blockIdx.x;
    const int tid = threadIdx.x;
    const float4 v = reinterpret_cast<const float4*>(x + (size_t)row * D_MODEL)[tid];

    float s = v.x + v.y + v.z + v.w;
    const float mean = block_sum(s, red) * (1.0f / D_MODEL);

    float4 d = make_float4(v.x - mean, v.y - mean, v.z - mean, v.w - mean);
    float sq = d.x*d.x + d.y*d.y + d.z*d.z + d.w*d.w;
    const float var = block_sum(sq, red) * (1.0f / (D_MODEL - 1));
    const float rstd = rsqrtf(var);

    const float4 a = reinterpret_cast<const float4*>(ga)[tid];
    const float4 b = reinterpret_cast<const float4*>(gb)[tid];
    float4 o;
    o.x = d.x * rstd * a.x + b.x;
    o.y = d.y * rstd * a.y + b.y;
    o.z = d.z * rstd * a.z + b.z;
    o.w = d.w * rstd * a.w + b.w;
    reinterpret_cast<float4*>(out + (size_t)row * D_MODEL)[tid] = o;
}

// ---------------- fp32 GEMM  C[M,N] = A[M,K] @ W[N,K]^T  (+epilogue) -------
// BM=BN=128, BK=8, 256 threads, 8x8 per thread via f32x2 packed FMA.
template<bool RELU, bool HASB, bool HASR>
__global__ __launch_bounds__(256) void gemm_kernel(
    const float* __restrict__ A, const float* __restrict__ W,
    const float* __restrict__ bias, const float* __restrict__ res,
    float* __restrict__ C, int M, int N, int K)
{
    __shared__ float As[8][128];
    __shared__ float Ws[8][128];

    const int tid = threadIdx.x;
    const int tx  = tid & 15;
    const int ty  = tid >> 4;
    const int bm  = blockIdx.y << 7;
    const int bn  = blockIdx.x << 7;
    const int lr  = tid >> 1;          // 0..127
    const int lk  = (tid & 1) << 2;    // 0 or 4

    const float* Ap = A + (size_t)(bm + lr) * K + lk;
    const float* Wp = W + (size_t)(bn + lr) * K + lk;

    float2 c2[8][4];
    #pragma unroll
    for (int i = 0; i < 8; i++)
        #pragma unroll
        for (int j = 0; j < 4; j++) c2[i][j] = make_float2(0.f, 0.f);

    float4 ra = *(const float4*)Ap;
    float4 rw = *(const float4*)Wp;

    const int nk = K >> 3;
    for (int kt = 0; kt < nk; ++kt) {
        As[lk+0][lr] = ra.x; As[lk+1][lr] = ra.y;
        As[lk+2][lr] = ra.z; As[lk+3][lr] = ra.w;
        Ws[lk+0][lr] = rw.x; Ws[lk+1][lr] = rw.y;
        Ws[lk+2][lr] = rw.z; Ws[lk+3][lr] = rw.w;
        __syncthreads();

        if (kt + 1 < nk) {   // prefetch next tile into registers
            ra = *(const float4*)(Ap + (size_t)(kt + 1) * 8);
            rw = *(const float4*)(Wp + (size_t)(kt + 1) * 8);
        }

        #pragma unroll
        for (int k = 0; k < 8; k++) {
            const float4 a0 = *(const float4*)&As[k][(ty << 2)];
            const float4 a1 = *(const float4*)&As[k][64 + (ty << 2)];
            const float4 b0 = *(const float4*)&Ws[k][(tx << 2)];
            const float4 b1 = *(const float4*)&Ws[k][64 + (tx << 2)];
            const float av[8] = {a0.x, a0.y, a0.z, a0.w, a1.x, a1.y, a1.z, a1.w};
            const float2 bv[4] = {make_float2(b0.x, b0.y), make_float2(b0.z, b0.w),
                                  make_float2(b1.x, b1.y), make_float2(b1.z, b1.w)};
            #pragma unroll
            for (int i = 0; i < 8; i++) {
                const float2 aa = make_float2(av[i], av[i]);
                #pragma unroll
                for (int j = 0; j < 4; j++) ffma2(c2[i][j], aa, bv[j]);
            }
        }
        __syncthreads();
    }

    float4 bb0 = make_float4(0,0,0,0), bb1 = make_float4(0,0,0,0);
    if (HASB) {
        bb0 = *(const float4*)(bias + bn + (tx << 2));
        bb1 = *(const float4*)(bias + bn + 64 + (tx << 2));
    }

    #pragma unroll
    for (int i = 0; i < 8; i++) {
        const int row = bm + ((i < 4) ? ((ty << 2) + i) : (64 + (ty << 2) + (i - 4)));
        float4 v0 = make_float4(c2[i][0].x, c2[i][0].y, c2[i][1].x, c2[i][1].y);
        float4 v1 = make_float4(c2[i][2].x, c2[i][2].y, c2[i][3].x, c2[i][3].y);
        if (HASB) {
            v0.x += bb0.x; v0.y += bb0.y; v0.z += bb0.z; v0.w += bb0.w;
            v1.x += bb1.x; v1.y += bb1.y; v1.z += bb1.z; v1.w += bb1.w;
        }
        if (RELU) {
            v0.x = fmaxf(v0.x, 0.f); v0.y = fmaxf(v0.y, 0.f);
            v0.z = fmaxf(v0.z, 0.f); v0.w = fmaxf(v0.w, 0.f);
            v1.x = fmaxf(v1.x, 0.f); v1.y = fmaxf(v1.y, 0.f);
            v1.z = fmaxf(v1.z, 0.f); v1.w = fmaxf(v1.w, 0.f);
        }
        const size_t base = (size_t)row * N + bn;
        if (HASR) {
            const float4 r0 = *(const float4*)(res + base + (tx << 2));
            const float4 r1 = *(const float4*)(res + base + 64 + (tx << 2));
            v0.x += r0.x; v0.y += r0.y; v0.z += r0.z; v0.w += r0.w;
            v1.x += r1.x; v1.y += r1.y; v1.z += r1.z; v1.w += r1.w;
        }
        *(float4*)(C + base + (tx << 2))      = v0;
        *(float4*)(C + base + 64 + (tx << 2)) = v1;
    }
}

// ---------------- flash attention (fp32 SIMT, online softmax) --------------
#define QT  32
#define KBS 32
#define KST 68   // padded row stride for K/V tiles (64 dims + 4)

__global__ __launch_bounds__(256) void attn_kernel(
    const float* __restrict__ Q, const float* __restrict__ Kg,
    const float* __restrict__ Vg, const int* __restrict__ mask,
    float* __restrict__ O)
{
    __shared__ float Qs[QT][DKH];
    __shared__ float Ks[KBS][KST];
    __shared__ float Vs[KBS][KST];
    __shared__ float Ss[QT][KBS + 1];
    __shared__ float pfac[QT], lrow[QT];
    __shared__ float mskv[KBS];

    const int tid = threadIdx.x;
    const int q0  = blockIdx.x * QT;
    const int h   = blockIdx.y;
    const int b   = blockIdx.z;
    const size_t hoff = (size_t)h * DKH;

    // load Q tile (32 x 64)
    {
        int slot = tid;
        #pragma unroll
        for (int it = 0; it < 2; ++it, slot += 256) {
            const int r = slot >> 4;
            const int c = (slot & 15) << 2;
            *(float4*)&Qs[r][c] =
                *(const float4*)(Q + (size_t)(b * SEQ + q0 + r) * D_MODEL + hoff + c);
        }
    }

    const int rq = tid >> 3;      // query row (0..31)
    const int lj = tid & 7;       // lane-in-row
    float2 o0 = make_float2(0,0), o1 = o0, o2 = o0, o3 = o0;
    float m_r = -INFINITY, l_r = 0.f;   // live only for tid<32

    for (int k0 = 0; k0 < SEQ; k0 += KBS) {
        __syncthreads();   // previous iter done with Ks/Vs/Ss
        {
            int slot = tid;
            #pragma unroll
            for (int it = 0; it < 2; ++it, slot += 256) {
                const int r = slot >> 4;
                const int c = (slot & 15) << 2;
                const size_t g = (size_t)(b * SEQ + k0 + r) * D_MODEL + hoff + c;
                *(float4*)&Ks[r][c] = *(const float4*)(Kg + g);
                *(float4*)&Vs[r][c] = *(const float4*)(Vg + g);
            }
            // mask arrives as int32 (bool normalized by the harness)
            if (tid < KBS) mskv[tid] = (float)mask[(size_t)b * SEQ + k0 + tid];
        }
        __syncthreads();

        // scores: each thread does 4 (rq, j) dot products over 64 dims
        {
            float2 acc[4];
            acc[0] = acc[1] = acc[2] = acc[3] = make_float2(0.f, 0.f);
            #pragma unroll
            for (int k4 = 0; k4 < 16; k4++) {
                const float4 q = *(const float4*)&Qs[rq][k4 << 2];
                const float2 qa = make_float2(q.x, q.y);
                const float2 qb = make_float2(q.z, q.w);
                #pragma unroll
                for (int jj = 0; jj < 4; jj++) {
                    const float4 kk = *(const float4*)&Ks[lj + (jj << 3)][k4 << 2];
                    ffma2(acc[jj], qa, make_float2(kk.x, kk.y));
                    ffma2(acc[jj], qb, make_float2(kk.z, kk.w));
                }
            }
            #pragma unroll
            for (int jj = 0; jj < 4; jj++) {
                const int j = lj + (jj << 3);
                float s = acc[jj].x + acc[jj].y;
                s = (mskv[j] != 0.f) ? -1e9f : s * 0.125f;
                Ss[rq][j] = s;
            }
        }
        __syncthreads();

        // online softmax (one thread per query row)
        if (tid < QT) {
            float bm = -INFINITY;
            #pragma unroll
            for (int j = 0; j < KBS; j++) bm = fmaxf(bm, Ss[tid][j]);
            const float nm  = fmaxf(m_r, bm);
            const float fac = __expf(m_r - nm);
            float l = l_r * fac;
            #pragma unroll
            for (int j = 0; j < KBS; j++) {
                const float p = __expf(Ss[tid][j] - nm);
                Ss[tid][j] = p;
                l += p;
            }
            m_r = nm; l_r = l;
            pfac[tid] = fac;
        }
        __syncthreads();

        // O = O*fac + P @ V
        {
            const float fac = pfac[rq];
            o0.x *= fac; o0.y *= fac; o1.x *= fac; o1.y *= fac;
            o2.x *= fac; o2.y *= fac; o3.x *= fac; o3.y *= fac;
            const int d0 = lj << 2;
            #pragma unroll
            for (int j = 0; j < KBS; j++) {
                const float p = Ss[rq][j];
                const float2 pp = make_float2(p, p);
                const float4 v0 = *(const float4*)&Vs[j][d0];
                const float4 v1 = *(const float4*)&Vs[j][32 + d0];
                ffma2(o0, pp, make_float2(v0.x, v0.y));
                ffma2(o1, pp, make_float2(v0.z, v0.w));
                ffma2(o2, pp, make_float2(v1.x, v1.y));
                ffma2(o3, pp, make_float2(v1.z, v1.w));
            }
        }
    }

    if (tid < QT) lrow[tid] = l_r;
    __syncthreads();
    {
        const float inv = 1.f / lrow[rq];
        const int d0 = lj << 2;
        float* op = O + (size_t)(b * SEQ + q0 + rq) * D_MODEL + hoff;
        *(float4*)(op + d0)      = make_float4(o0.x*inv, o0.y*inv, o1.x*inv, o1.y*inv);
        *(float4*)(op + 32 + d0) = make_float4(o2.x*inv, o2.y*inv, o3.x*inv, o3.y*inv);
    }
}

// ---------------- launch --------------------------------------------------
extern "C" void kernel_launch(void* const* d_in, const int* in_sizes, int n_in,
                              void* d_out, int out_size)
{
    const float* x     = (const float*)d_in[0];
    const float* w_q   = (const float*)d_in[1];
    const float* w_k   = (const float*)d_in[2];
    const float* w_v   = (const float*)d_in[3];
    const float* w_o   = (const float*)d_in[4];
    const float* l1_w  = (const float*)d_in[5];
    const float* l1_b  = (const float*)d_in[6];
    const float* l2_w  = (const float*)d_in[7];
    const float* l2_b  = (const float*)d_in[8];
    const float* n1a   = (const float*)d_in[9];
    const float* n1b   = (const float*)d_in[10];
    const float* n2a   = (const float*)d_in[11];
    const float* n2b   = (const float*)d_in[12];
    const float* nfa   = (const float*)d_in[13];
    const float* nfb   = (const float*)d_in[14];
    const int*   mask  = (const int*)d_in[15];
    float* out = (float*)d_out;

    float *xn, *q, *k, *v, *ao, *x1, *hb, *ff, *x2;
    cudaGetSymbolAddress((void**)&xn, g_xn);
    cudaGetSymbolAddress((void**)&q,  g_q);
    cudaGetSymbolAddress((void**)&k,  g_k);
    cudaGetSymbolAddress((void**)&v,  g_v);
    cudaGetSymbolAddress((void**)&ao, g_ao);
    cudaGetSymbolAddress((void**)&x1, g_x1);
    cudaGetSymbolAddress((void**)&hb, g_h);
    cudaGetSymbolAddress((void**)&ff, g_ff);
    cudaGetSymbolAddress((void**)&x2, g_x2);

    const dim3 gD(D_MODEL / 128, NROWS / 128);   // N=1024 GEMMs
    const dim3 gF(D_FF    / 128, NROWS / 128);   // N=4096 GEMM

    // 1) xn = LN1(x)
    ln_kernel<<<NROWS, 256>>>(x, n1a, n1b, xn);
    // 2) Q,K,V
    gemm_kernel<false,false,false><<<gD, 256>>>(xn, w_q, nullptr, nullptr, q,  NROWS, D_MODEL, D_MODEL);
    gemm_kernel<false,false,false><<<gD, 256>>>(xn, w_k, nullptr, nullptr, k,  NROWS, D_MODEL, D_MODEL);
    gemm_kernel<false,false,false><<<gD, 256>>>(xn, w_v, nullptr, nullptr, v,  NROWS, D_MODEL, D_MODEL);
    // 3) attention
    attn_kernel<<<dim3(SEQ/QT, NH, BATCH), 256>>>(q, k, v, mask, ao);
    // 4) x1 = x + ao @ w_o^T
    gemm_kernel<false,false,true><<<gD, 256>>>(ao, w_o, nullptr, x, x1, NROWS, D_MODEL, D_MODEL);
    // 5) h = LN2(x1)
    ln_kernel<<<NROWS, 256>>>(x1, n2a, n2b, hb);
    // 6) ff = relu(h @ l1_w^T + l1_b)
    gemm_kernel<true,true,false><<<gF, 256>>>(hb, l1_w, l1_b, nullptr, ff, NROWS, D_FF, D_MODEL);
    // 7) x2 = x1 + ff @ l2_w^T + l2_b
    gemm_kernel<false,true,true><<<gD, 256>>>(ff, l2_w, l2_b, x1, x2, NROWS, D_MODEL, D_FF);
    // 8) out = LNf(x2)
    ln_kernel<<<NROWS, 256>>>(x2, nfa, nfb, out);
}

// round 4
// speedup vs baseline: 1.2969x; 1.2969x over previous
#include <cuda_runtime.h>
#include <cuda_bf16.h>
#include <math.h>
#include <stdint.h>

#define D_MODEL 1024
#define NH      16
#define DKH     64
#define D_FF    4096
#define BATCH   4
#define SEQ     2048
#define NROWS   (BATCH*SEQ)

typedef __nv_bfloat16 bf16;

// ---------------- scratch (device globals; no runtime allocation) ----------
__device__ float g_q [NROWS * D_MODEL];
__device__ float g_k [NROWS * D_MODEL];
__device__ float g_v [NROWS * D_MODEL];
__device__ float g_x1[NROWS * D_MODEL];
__device__ float g_x2[NROWS * D_MODEL];

__device__ bf16 g_xnh[NROWS * D_MODEL], g_xnl[NROWS * D_MODEL];
__device__ bf16 g_hh [NROWS * D_MODEL], g_hl [NROWS * D_MODEL];
__device__ bf16 g_aoh[NROWS * D_MODEL], g_aol[NROWS * D_MODEL];
__device__ bf16 g_ffh[(size_t)NROWS * D_FF], g_ffl[(size_t)NROWS * D_FF];

__device__ bf16 g_wqh[D_MODEL*D_MODEL], g_wql[D_MODEL*D_MODEL];
__device__ bf16 g_wkh[D_MODEL*D_MODEL], g_wkl[D_MODEL*D_MODEL];
__device__ bf16 g_wvh[D_MODEL*D_MODEL], g_wvl[D_MODEL*D_MODEL];
__device__ bf16 g_woh[D_MODEL*D_MODEL], g_wol[D_MODEL*D_MODEL];
__device__ bf16 g_l1h[D_FF*D_MODEL],   g_l1l[D_FF*D_MODEL];
__device__ bf16 g_l2h[D_MODEL*D_FF],   g_l2l[D_MODEL*D_FF];

// ---------------- small PTX helpers ----------------------------------------
__device__ __forceinline__ uint32_t smem_u32(const void* p) {
    uint32_t a;
    asm("{ .reg .u64 t; cvta.to.shared.u64 t, %1; cvt.u32.u64 %0, t; }"
        : "=r"(a) : "l"(p));
    return a;
}
__device__ __forceinline__ void cpasync16(uint32_t dst, const void* src) {
    asm volatile("cp.async.cg.shared.global [%0], [%1], 16;"
                 :: "r"(dst), "l"(src));
}
#define CP_COMMIT() asm volatile("cp.async.commit_group;" ::: "memory")
#define CP_WAIT1()  asm volatile("cp.async.wait_group 1;" ::: "memory")

__device__ __forceinline__ void ldm4(uint32_t* r, uint32_t addr) {
    asm volatile("ldmatrix.sync.aligned.m8n8.x4.shared.b16 {%0,%1,%2,%3}, [%4];"
        : "=r"(r[0]), "=r"(r[1]), "=r"(r[2]), "=r"(r[3]) : "r"(addr));
}
__device__ __forceinline__ void mma16816(float* c, const uint32_t* a,
                                         uint32_t b0, uint32_t b1) {
    asm volatile("mma.sync.aligned.m16n8k16.row.col.f32.bf16.bf16.f32 "
        "{%0,%1,%2,%3}, {%4,%5,%6,%7}, {%8,%9}, {%0,%1,%2,%3};"
        : "+f"(c[0]), "+f"(c[1]), "+f"(c[2]), "+f"(c[3])
        : "r"(a[0]), "r"(a[1]), "r"(a[2]), "r"(a[3]), "r"(b0), "r"(b1));
}

__device__ __forceinline__ void split_bf16(float f, bf16& h, bf16& l) {
    h = __float2bfloat16_rn(f);
    l = __float2bfloat16_rn(f - __bfloat162float(h));
}

// ---------------- packed fp32x2 FMA (attention) -----------------------------
__device__ __forceinline__ void ffma2(float2& d, float2 a, float2 b) {
    asm("fma.rn.f32x2 %0, %1, %2, %0;"
        : "+l"(reinterpret_cast<unsigned long long&>(d))
        : "l"(reinterpret_cast<unsigned long long&>(a)),
          "l"(reinterpret_cast<unsigned long long&>(b)));
}

// ---------------- weight fp32 -> bf16 hi/lo conversion ----------------------
__global__ __launch_bounds__(256) void cvt_kernel(
    const float4* __restrict__ src, ushort4* __restrict__ hi,
    ushort4* __restrict__ lo, int n4)
{
    int i = blockIdx.x * 256 + threadIdx.x;
    if (i >= n4) return;
    float4 v = src[i];
    bf16 h0,l0,h1,l1,h2,l2,h3,l3;
    split_bf16(v.x, h0, l0); split_bf16(v.y, h1, l1);
    split_bf16(v.z, h2, l2); split_bf16(v.w, h3, l3);
    hi[i] = make_ushort4(__bfloat16_as_ushort(h0), __bfloat16_as_ushort(h1),
                         __bfloat16_as_ushort(h2), __bfloat16_as_ushort(h3));
    lo[i] = make_ushort4(__bfloat16_as_ushort(l0), __bfloat16_as_ushort(l1),
                         __bfloat16_as_ushort(l2), __bfloat16_as_ushort(l3));
}

// ---------------- layernorm (unbiased std) ----------------------------------
__device__ __forceinline__ float block_sum(float v, float* red) {
    __syncthreads();
    #pragma unroll
    for (int o = 16; o; o >>= 1) v += __shfl_xor_sync(0xffffffffu, v, o);
    int tid = threadIdx.x;
    if ((tid & 31) == 0) red[tid >> 5] = v;
    __syncthreads();
    if (tid == 0) {
        float t = 0.f;
        #pragma unroll
        for (int i = 0; i < 8; i++) t += red[i];
        red[0] = t;
    }
    __syncthreads();
    return red[0];
}

template<bool BF16OUT>
__global__ __launch_bounds__(256) void ln_kernel(
    const float* __restrict__ x, const float* __restrict__ ga,
    const float* __restrict__ gb, float* __restrict__ out,
    bf16* __restrict__ oh, bf16* __restrict__ ol)
{
    __shared__ float red[8];
    const int row = blockIdx.x;
    const int tid = threadIdx.x;
    const float4 v = reinterpret_cast<const float4*>(x + (size_t)row * D_MODEL)[tid];

    float s = v.x + v.y + v.z + v.w;
    const float mean = block_sum(s, red) * (1.0f / D_MODEL);

    float4 d = make_float4(v.x - mean, v.y - mean, v.z - mean, v.w - mean);
    float sq = d.x*d.x + d.y*d.y + d.z*d.z + d.w*d.w;
    const float var = block_sum(sq, red) * (1.0f / (D_MODEL - 1));
    const float rstd = rsqrtf(var);

    const float4 a = reinterpret_cast<const float4*>(ga)[tid];
    const float4 b = reinterpret_cast<const float4*>(gb)[tid];
    float4 o;
    o.x = d.x * rstd * a.x + b.x;
    o.y = d.y * rstd * a.y + b.y;
    o.z = d.z * rstd * a.z + b.z;
    o.w = d.w * rstd * a.w + b.w;
    if (BF16OUT) {
        bf16 h0,l0,h1,l1,h2,l2,h3,l3;
        split_bf16(o.x, h0, l0); split_bf16(o.y, h1, l1);
        split_bf16(o.z, h2, l2); split_bf16(o.w, h3, l3);
        const size_t idx = (size_t)row * (D_MODEL/4) + tid;
        reinterpret_cast<ushort4*>(oh)[idx] =
            make_ushort4(__bfloat16_as_ushort(h0), __bfloat16_as_ushort(h1),
                         __bfloat16_as_ushort(h2), __bfloat16_as_ushort(h3));
        reinterpret_cast<ushort4*>(ol)[idx] =
            make_ushort4(__bfloat16_as_ushort(l0), __bfloat16_as_ushort(l1),
                         __bfloat16_as_ushort(l2), __bfloat16_as_ushort(l3));
    } else {
        reinterpret_cast<float4*>(out + (size_t)row * D_MODEL)[tid] = o;
    }
}

// ---------------- mma.sync bf16x3-split GEMM --------------------------------
// C[M,N] = A[M,K] @ W[N,K]^T. BM=BN=128, BK=32, 3-stage cp.async pipeline.
// 8 warps in 4(M)x2(N) grid; each warp 32x64 via m16n8k16 HMMA, 3 split passes.
#define NSTG      3
#define ROWB      80                    // padded row stride: 32 halves + 8 pad
#define TILE_B    (128*ROWB)            // 10240 B: one 128x32 bf16 tile
#define STAGE_B   (4*TILE_B)            // Ahi, Alo, Whi, Wlo
#define GEMM_SMEM (NSTG*STAGE_B)        // 122880 B

template<bool RELU, bool HASB, bool HASR, bool BF16OUT>
__global__ __launch_bounds__(256) void gemm_tc(
    const bf16* __restrict__ Ah, const bf16* __restrict__ Al,
    const bf16* __restrict__ Wh, const bf16* __restrict__ Wl,
    const float* __restrict__ bias, const float* __restrict__ res,
    float* __restrict__ C, bf16* __restrict__ Ch, bf16* __restrict__ Cl,
    int M, int N, int K)
{
    extern __shared__ char smem[];
    const uint32_t sb = smem_u32(smem);
    const int tid  = threadIdx.x;
    const int bm   = blockIdx.y << 7;
    const int bn   = blockIdx.x << 7;
    const int w    = tid >> 5, lane = tid & 31;
    const int mblock = (w & 3) << 5;     // 0,32,64,96
    const int nblock = (w >> 2) << 6;    // 0,64

    // ldmatrix per-lane byte offsets inside a tile
    const uint32_t aRowByte = (uint32_t)(mblock + (lane & 15)) * ROWB
                            + ((lane >> 4) & 1) * 16;
    const uint32_t bRowByte = (uint32_t)(nblock + ((lane >> 4) << 3) + (lane & 7)) * ROWB
                            + ((lane >> 3) & 1) * 16;

    float acc[2][8][4];
    #pragma unroll
    for (int i = 0; i < 2; i++)
        #pragma unroll
        for (int j = 0; j < 8; j++)
            #pragma unroll
            for (int t = 0; t < 4; t++) acc[i][j][t] = 0.f;

    // one 128x32 bf16 tile = 512 16B-chunks; 2 chunks per thread
    auto load1 = [&](const bf16* __restrict__ src, int row0, uint32_t sbase, int kt) {
        #pragma unroll
        for (int i = 0; i < 2; i++) {
            const int ch = tid + (i << 8);
            const int r = ch >> 2, c = ch & 3;
            cpasync16(sbase + (uint32_t)r * ROWB + c * 16,
                      src + (size_t)(row0 + r) * K + (kt << 5) + (c << 3));
        }
    };
    auto load_stage = [&](int kt, int slot) {
        const uint32_t base = sb + slot * STAGE_B;
        load1(Ah, bm, base,            kt);
        load1(Al, bm, base + TILE_B,   kt);
        load1(Wh, bn, base + 2*TILE_B, kt);
        load1(Wl, bn, base + 3*TILE_B, kt);
    };

    const int NK = K >> 5;
    load_stage(0, 0); CP_COMMIT();
    load_stage(1, 1); CP_COMMIT();

    for (int kt = 0; kt < NK; ++kt) {
        CP_WAIT1();
        __syncthreads();

        const uint32_t st = sb + (kt % NSTG) * STAGE_B;
        const uint32_t aHi = st + aRowByte;
        const uint32_t aLo = aHi + TILE_B;
        const uint32_t bHi = st + 2*TILE_B + bRowByte;
        const uint32_t bLo = bHi + TILE_B;

        #pragma unroll
        for (int ks = 0; ks < 2; ++ks) {
            uint32_t ah[2][4], al[2][4], bh[4][4], bl[4][4];
            #pragma unroll
            for (int mt = 0; mt < 2; mt++) {
                ldm4(ah[mt], aHi + mt*(16*ROWB) + ks*32);
                ldm4(al[mt], aLo + mt*(16*ROWB) + ks*32);
            }
            #pragma unroll
            for (int np = 0; np < 4; np++) {
                ldm4(bh[np], bHi + np*(16*ROWB) + ks*32);
                ldm4(bl[np], bLo + np*(16*ROWB) + ks*32);
            }
            #pragma unroll
            for (int mt = 0; mt < 2; mt++)
                #pragma unroll
                for (int np = 0; np < 4; np++)
                    #pragma unroll
                    for (int h = 0; h < 2; h++) {
                        float* c = acc[mt][np*2 + h];
                        mma16816(c, ah[mt], bh[np][h*2], bh[np][h*2+1]);
                        mma16816(c, ah[mt], bl[np][h*2], bl[np][h*2+1]);
                        mma16816(c, al[mt], bh[np][h*2], bh[np][h*2+1]);
                    }
        }
        __syncthreads();

        const int nt = kt + 2;
        if (nt < NK) load_stage(nt, nt % NSTG);
        CP_COMMIT();
    }

    // ---------------- epilogue ----------------
    #pragma unroll
    for (int mt = 0; mt < 2; mt++) {
        #pragma unroll
        for (int nt = 0; nt < 8; nt++) {
            const int r0 = bm + mblock + mt*16 + (lane >> 2);
            const int c0 = bn + nblock + nt*8 + ((lane & 3) << 1);
            float v00 = acc[mt][nt][0], v01 = acc[mt][nt][1];
            float v10 = acc[mt][nt][2], v11 = acc[mt][nt][3];
            if (HASB) {
                const float2 bb = *(const float2*)(bias + c0);
                v00 += bb.x; v01 += bb.y; v10 += bb.x; v11 += bb.y;
            }
            if (RELU) {
                v00 = fmaxf(v00, 0.f); v01 = fmaxf(v01, 0.f);
                v10 = fmaxf(v10, 0.f); v11 = fmaxf(v11, 0.f);
            }
            const size_t o0 = (size_t)r0 * N + c0;
            const size_t o1 = o0 + (size_t)8 * N;
            if (HASR) {
                const float2 r4a = *(const float2*)(res + o0);
                const float2 r4b = *(const float2*)(res + o1);
                v00 += r4a.x; v01 += r4a.y; v10 += r4b.x; v11 += r4b.y;
            }
            if (BF16OUT) {
                bf16 h0,l0,h1,l1;
                split_bf16(v00, h0, l0); split_bf16(v01, h1, l1);
                *(ushort2*)(Ch + o0) = make_ushort2(__bfloat16_as_ushort(h0),
                                                    __bfloat16_as_ushort(h1));
                *(ushort2*)(Cl + o0) = make_ushort2(__bfloat16_as_ushort(l0),
                                                    __bfloat16_as_ushort(l1));
                split_bf16(v10, h0, l0); split_bf16(v11, h1, l1);
                *(ushort2*)(Ch + o1) = make_ushort2(__bfloat16_as_ushort(h0),
                                                    __bfloat16_as_ushort(h1));
                *(ushort2*)(Cl + o1) = make_ushort2(__bfloat16_as_ushort(l0),
                                                    __bfloat16_as_ushort(l1));
            } else {
                *(float2*)(C + o0) = make_float2(v00, v01);
                *(float2*)(C + o1) = make_float2(v10, v11);
            }
        }
    }
}

// ---------------- flash attention (fp32 SIMT, bf16 hi/lo output) ------------
#define QT  32
#define KBS 32
#define KST 68

__global__ __launch_bounds__(256) void attn_kernel(
    const float* __restrict__ Q, const float* __restrict__ Kg,
    const float* __restrict__ Vg, const int* __restrict__ mask,
    bf16* __restrict__ Oh, bf16* __restrict__ Ol)
{
    __shared__ float Qs[QT][DKH];
    __shared__ float Ks[KBS][KST];
    __shared__ float Vs[KBS][KST];
    __shared__ float Ss[QT][KBS + 1];
    __shared__ float pfac[QT], lrow[QT];
    __shared__ float mskv[KBS];

    const int tid = threadIdx.x;
    const int q0  = blockIdx.x * QT;
    const int h   = blockIdx.y;
    const int b   = blockIdx.z;
    const size_t hoff = (size_t)h * DKH;

    {
        int slot = tid;
        #pragma unroll
        for (int it = 0; it < 2; ++it, slot += 256) {
            const int r = slot >> 4;
            const int c = (slot & 15) << 2;
            *(float4*)&Qs[r][c] =
                *(const float4*)(Q + (size_t)(b * SEQ + q0 + r) * D_MODEL + hoff + c);
        }
    }

    const int rq = tid >> 3;
    const int lj = tid & 7;
    float2 o0 = make_float2(0,0), o1 = o0, o2 = o0, o3 = o0;
    float m_r = -INFINITY, l_r = 0.f;

    for (int k0 = 0; k0 < SEQ; k0 += KBS) {
        __syncthreads();
        {
            int slot = tid;
            #pragma unroll
            for (int it = 0; it < 2; ++it, slot += 256) {
                const int r = slot >> 4;
                const int c = (slot & 15) << 2;
                const size_t g = (size_t)(b * SEQ + k0 + r) * D_MODEL + hoff + c;
                *(float4*)&Ks[r][c] = *(const float4*)(Kg + g);
                *(float4*)&Vs[r][c] = *(const float4*)(Vg + g);
            }
            if (tid < KBS) mskv[tid] = (float)mask[(size_t)b * SEQ + k0 + tid];
        }
        __syncthreads();

        {
            float2 acc[4];
            acc[0] = acc[1] = acc[2] = acc[3] = make_float2(0.f, 0.f);
            #pragma unroll
            for (int k4 = 0; k4 < 16; k4++) {
                const float4 q = *(const float4*)&Qs[rq][k4 << 2];
                const float2 qa = make_float2(q.x, q.y);
                const float2 qb = make_float2(q.z, q.w);
                #pragma unroll
                for (int jj = 0; jj < 4; jj++) {
                    const float4 kk = *(const float4*)&Ks[lj + (jj << 3)][k4 << 2];
                    ffma2(acc[jj], qa, make_float2(kk.x, kk.y));
                    ffma2(acc[jj], qb, make_float2(kk.z, kk.w));
                }
            }
            #pragma unroll
            for (int jj = 0; jj < 4; jj++) {
                const int j = lj + (jj << 3);
                float s = acc[jj].x + acc[jj].y;
                s = (mskv[j] != 0.f) ? -1e9f : s * 0.125f;
                Ss[rq][j] = s;
            }
        }
        __syncthreads();

        if (tid < QT) {
            float bm = -INFINITY;
            #pragma unroll
            for (int j = 0; j < KBS; j++) bm = fmaxf(bm, Ss[tid][j]);
            const float nm  = fmaxf(m_r, bm);
            const float fac = __expf(m_r - nm);
            float l = l_r * fac;
            #pragma unroll
            for (int j = 0; j < KBS; j++) {
                const float p = __expf(Ss[tid][j] - nm);
                Ss[tid][j] = p;
                l += p;
            }
            m_r = nm; l_r = l;
            pfac[tid] = fac;
        }
        __syncthreads();

        {
            const float fac = pfac[rq];
            o0.x *= fac; o0.y *= fac; o1.x *= fac; o1.y *= fac;
            o2.x *= fac; o2.y *= fac; o3.x *= fac; o3.y *= fac;
            const int d0 = lj << 2;
            #pragma unroll
            for (int j = 0; j < KBS; j++) {
                const float p = Ss[rq][j];
                const float2 pp = make_float2(p, p);
                const float4 v0 = *(const float4*)&Vs[j][d0];
                const float4 v1 = *(const float4*)&Vs[j][32 + d0];
                ffma2(o0, pp, make_float2(v0.x, v0.y));
                ffma2(o1, pp, make_float2(v0.z, v0.w));
                ffma2(o2, pp, make_float2(v1.x, v1.y));
                ffma2(o3, pp, make_float2(v1.z, v1.w));
            }
        }
    }

    if (tid < QT) lrow[tid] = l_r;
    __syncthreads();
    {
        const float inv = 1.f / lrow[rq];
        const int d0 = lj << 2;
        const size_t ob = (size_t)(b * SEQ + q0 + rq) * D_MODEL + hoff;
        float vout[8] = {o0.x*inv, o0.y*inv, o1.x*inv, o1.y*inv,
                         o2.x*inv, o2.y*inv, o3.x*inv, o3.y*inv};
        #pragma unroll
        for (int g = 0; g < 2; g++) {
            bf16 h4[4], l4[4];
            #pragma unroll
            for (int j = 0; j < 4; j++) split_bf16(vout[g*4+j], h4[j], l4[j]);
            const size_t idx = ob + (g ? (32 + d0) : d0);
            *(ushort4*)(Oh + idx) =
                make_ushort4(__bfloat16_as_ushort(h4[0]), __bfloat16_as_ushort(h4[1]),
                             __bfloat16_as_ushort(h4[2]), __bfloat16_as_ushort(h4[3]));
            *(ushort4*)(Ol + idx) =
                make_ushort4(__bfloat16_as_ushort(l4[0]), __bfloat16_as_ushort(l4[1]),
                             __bfloat16_as_ushort(l4[2]), __bfloat16_as_ushort(l4[3]));
        }
    }
}

// ---------------- launch -----------------------------------------------------
extern "C" void kernel_launch(void* const* d_in, const int* in_sizes, int n_in,
                              void* d_out, int out_size)
{
    const float* x     = (const float*)d_in[0];
    const float* w_q   = (const float*)d_in[1];
    const float* w_k   = (const float*)d_in[2];
    const float* w_v   = (const float*)d_in[3];
    const float* w_o   = (const float*)d_in[4];
    const float* l1_w  = (const float*)d_in[5];
    const float* l1_b  = (const float*)d_in[6];
    const float* l2_w  = (const float*)d_in[7];
    const float* l2_b  = (const float*)d_in[8];
    const float* n1a   = (const float*)d_in[9];
    const float* n1b   = (const float*)d_in[10];
    const float* n2a   = (const float*)d_in[11];
    const float* n2b   = (const float*)d_in[12];
    const float* nfa   = (const float*)d_in[13];
    const float* nfb   = (const float*)d_in[14];
    const int*   mask  = (const int*)d_in[15];
    float* out = (float*)d_out;

    float *q, *k, *v, *x1, *x2;
    bf16 *xnh,*xnl,*hh,*hl,*aoh,*aol,*ffh,*ffl;
    bf16 *wqh,*wql,*wkh,*wkl,*wvh,*wvl,*woh,*wol,*l1h,*l1l,*l2h,*l2l;
    cudaGetSymbolAddress((void**)&q,  g_q);
    cudaGetSymbolAddress((void**)&k,  g_k);
    cudaGetSymbolAddress((void**)&v,  g_v);
    cudaGetSymbolAddress((void**)&x1, g_x1);
    cudaGetSymbolAddress((void**)&x2, g_x2);
    cudaGetSymbolAddress((void**)&xnh, g_xnh); cudaGetSymbolAddress((void**)&xnl, g_xnl);
    cudaGetSymbolAddress((void**)&hh,  g_hh);  cudaGetSymbolAddress((void**)&hl,  g_hl);
    cudaGetSymbolAddress((void**)&aoh, g_aoh); cudaGetSymbolAddress((void**)&aol, g_aol);
    cudaGetSymbolAddress((void**)&ffh, g_ffh); cudaGetSymbolAddress((void**)&ffl, g_ffl);
    cudaGetSymbolAddress((void**)&wqh, g_wqh); cudaGetSymbolAddress((void**)&wql, g_wql);
    cudaGetSymbolAddress((void**)&wkh, g_wkh); cudaGetSymbolAddress((void**)&wkl, g_wkl);
    cudaGetSymbolAddress((void**)&wvh, g_wvh); cudaGetSymbolAddress((void**)&wvl, g_wvl);
    cudaGetSymbolAddress((void**)&woh, g_woh); cudaGetSymbolAddress((void**)&wol, g_wol);
    cudaGetSymbolAddress((void**)&l1h, g_l1h); cudaGetSymbolAddress((void**)&l1l, g_l1l);
    cudaGetSymbolAddress((void**)&l2h, g_l2h); cudaGetSymbolAddress((void**)&l2l, g_l2l);

    cudaFuncSetAttribute(gemm_tc<false,false,false,false>,
        cudaFuncAttributeMaxDynamicSharedMemorySize, GEMM_SMEM);
    cudaFuncSetAttribute(gemm_tc<false,false,true,false>,
        cudaFuncAttributeMaxDynamicSharedMemorySize, GEMM_SMEM);
    cudaFuncSetAttribute(gemm_tc<true,true,false,true>,
        cudaFuncAttributeMaxDynamicSharedMemorySize, GEMM_SMEM);
    cudaFuncSetAttribute(gemm_tc<false,true,true,false>,
        cudaFuncAttributeMaxDynamicSharedMemorySize, GEMM_SMEM);

    // weight conversions
    const int nDD4 = D_MODEL*D_MODEL/4, nFD4 = D_FF*D_MODEL/4;
    cvt_kernel<<<(nDD4+255)/256, 256>>>((const float4*)w_q,  (ushort4*)wqh, (ushort4*)wql, nDD4);
    cvt_kernel<<<(nDD4+255)/256, 256>>>((const float4*)w_k,  (ushort4*)wkh, (ushort4*)wkl, nDD4);
    cvt_kernel<<<(nDD4+255)/256, 256>>>((const float4*)w_v,  (ushort4*)wvh, (ushort4*)wvl, nDD4);
    cvt_kernel<<<(nDD4+255)/256, 256>>>((const float4*)w_o,  (ushort4*)woh, (ushort4*)wol, nDD4);
    cvt_kernel<<<(nFD4+255)/256, 256>>>((const float4*)l1_w, (ushort4*)l1h, (ushort4*)l1l, nFD4);
    cvt_kernel<<<(nFD4+255)/256, 256>>>((const float4*)l2_w, (ushort4*)l2h, (ushort4*)l2l, nFD4);

    const dim3 gD(D_MODEL/128, NROWS/128);
    const dim3 gF(D_FF/128,    NROWS/128);

    // 1) xn = LN1(x) -> bf16 hi/lo
    ln_kernel<true><<<NROWS, 256>>>(x, n1a, n1b, nullptr, xnh, xnl);
    // 2) Q,K,V (fp32 out)
    gemm_tc<false,false,false,false><<<gD, 256, GEMM_SMEM>>>(
        xnh, xnl, wqh, wql, nullptr, nullptr, q, nullptr, nullptr, NROWS, D_MODEL, D_MODEL);
    gemm_tc<false,false,false,false><<<gD, 256, GEMM_SMEM>>>(
        xnh, xnl, wkh, wkl, nullptr, nullptr, k, nullptr, nullptr, NROWS, D_MODEL, D_MODEL);
    gemm_tc<false,false,false,false><<<gD, 256, GEMM_SMEM>>>(
        xnh, xnl, wvh, wvl, nullptr, nullptr, v, nullptr, nullptr, NROWS, D_MODEL, D_MODEL);
    // 3) attention -> bf16 hi/lo
    attn_kernel<<<dim3(SEQ/QT, NH, BATCH), 256>>>(q, k, v, mask, aoh, aol);
    // 4) x1 = x + ao @ w_o^T (fp32)
    gemm_tc<false,false,true,false><<<gD, 256, GEMM_SMEM>>>(
        aoh, aol, woh, wol, nullptr, x, x1, nullptr, nullptr, NROWS, D_MODEL, D_MODEL);
    // 5) h = LN2(x1) -> bf16 hi/lo
    ln_kernel<true><<<NROWS, 256>>>(x1, n2a, n2b, nullptr, hh, hl);
    // 6) ff = relu(h @ l1^T + b1) -> bf16 hi/lo
    gemm_tc<true,true,false,true><<<gF, 256, GEMM_SMEM>>>(
        hh, hl, l1h, l1l, l1_b, nullptr, nullptr, ffh, ffl, NROWS, D_FF, D_MODEL);
    // 7) x2 = x1 + ff @ l2^T + b2 (fp32)
    gemm_tc<false,true,true,false><<<gD, 256, GEMM_SMEM>>>(
        ffh, ffl, l2h, l2l, l2_b, x1, x2, nullptr, nullptr, NROWS, D_MODEL, D_FF);
    // 8) out = LNf(x2)
    ln_kernel<false><<<NROWS, 256>>>(x2, nfa, nfb, out, nullptr, nullptr);
}

// round 5
// speedup vs baseline: 2.9939x; 2.3085x over previous
#include <cuda_runtime.h>
#include <cuda_bf16.h>
#include <math.h>
#include <stdint.h>

#define D_MODEL 1024
#define NH      16
#define DKH     64
#define D_FF    4096
#define BATCH   4
#define SEQ     2048
#define NROWS   (BATCH*SEQ)

typedef __nv_bfloat16 bf16;

// ---------------- scratch (device globals; no runtime allocation) ----------
__device__ float g_x1[NROWS * D_MODEL];
__device__ float g_x2[NROWS * D_MODEL];

__device__ bf16 g_xnh[NROWS * D_MODEL], g_xnl[NROWS * D_MODEL];
__device__ bf16 g_qh [NROWS * D_MODEL], g_ql [NROWS * D_MODEL];
__device__ bf16 g_kh [NROWS * D_MODEL], g_kl [NROWS * D_MODEL];
__device__ bf16 g_vh [NROWS * D_MODEL], g_vl [NROWS * D_MODEL];
__device__ bf16 g_hh [NROWS * D_MODEL], g_hl [NROWS * D_MODEL];
__device__ bf16 g_aoh[NROWS * D_MODEL], g_aol[NROWS * D_MODEL];
__device__ bf16 g_ffh[(size_t)NROWS * D_FF], g_ffl[(size_t)NROWS * D_FF];

__device__ bf16 g_wqh[D_MODEL*D_MODEL], g_wql[D_MODEL*D_MODEL];
__device__ bf16 g_wkh[D_MODEL*D_MODEL], g_wkl[D_MODEL*D_MODEL];
__device__ bf16 g_wvh[D_MODEL*D_MODEL], g_wvl[D_MODEL*D_MODEL];
__device__ bf16 g_woh[D_MODEL*D_MODEL], g_wol[D_MODEL*D_MODEL];
__device__ bf16 g_l1h[D_FF*D_MODEL],   g_l1l[D_FF*D_MODEL];
__device__ bf16 g_l2h[D_MODEL*D_FF],   g_l2l[D_MODEL*D_FF];

// ---------------- small PTX helpers ----------------------------------------
__device__ __forceinline__ uint32_t smem_u32(const void* p) {
    uint32_t a;
    asm("{ .reg .u64 t; cvta.to.shared.u64 t, %1; cvt.u32.u64 %0, t; }"
        : "=r"(a) : "l"(p));
    return a;
}
__device__ __forceinline__ void cpasync16(uint32_t dst, const void* src) {
    asm volatile("cp.async.cg.shared.global [%0], [%1], 16;"
                 :: "r"(dst), "l"(src));
}
#define CP_COMMIT() asm volatile("cp.async.commit_group;" ::: "memory")
#define CP_WAIT1()  asm volatile("cp.async.wait_group 1;" ::: "memory")
#define CP_WAIT0()  asm volatile("cp.async.wait_group 0;" ::: "memory")

__device__ __forceinline__ void ldm4(uint32_t* r, uint32_t addr) {
    asm volatile("ldmatrix.sync.aligned.m8n8.x4.shared.b16 {%0,%1,%2,%3}, [%4];"
        : "=r"(r[0]), "=r"(r[1]), "=r"(r[2]), "=r"(r[3]) : "r"(addr));
}
__device__ __forceinline__ void ldm4t(uint32_t* r, uint32_t addr) {
    asm volatile("ldmatrix.sync.aligned.m8n8.x4.trans.shared.b16 {%0,%1,%2,%3}, [%4];"
        : "=r"(r[0]), "=r"(r[1]), "=r"(r[2]), "=r"(r[3]) : "r"(addr));
}
__device__ __forceinline__ void mma16816(float* c, const uint32_t* a,
                                         uint32_t b0, uint32_t b1) {
    asm volatile("mma.sync.aligned.m16n8k16.row.col.f32.bf16.bf16.f32 "
        "{%0,%1,%2,%3}, {%4,%5,%6,%7}, {%8,%9}, {%0,%1,%2,%3};"
        : "+f"(c[0]), "+f"(c[1]), "+f"(c[2]), "+f"(c[3])
        : "r"(a[0]), "r"(a[1]), "r"(a[2]), "r"(a[3]), "r"(b0), "r"(b1));
}

__device__ __forceinline__ void split_bf16(float f, bf16& h, bf16& l) {
    h = __float2bfloat16_rn(f);
    l = __float2bfloat16_rn(f - __bfloat162float(h));
}
__device__ __forceinline__ uint32_t packbf(bf16 a, bf16 b) {
    return (uint32_t)__bfloat16_as_ushort(a) |
           ((uint32_t)__bfloat16_as_ushort(b) << 16);
}

// ---------------- weight fp32 -> bf16 hi/lo conversion ----------------------
__global__ __launch_bounds__(256) void cvt_kernel(
    const float4* __restrict__ src, ushort4* __restrict__ hi,
    ushort4* __restrict__ lo, int n4)
{
    int i = blockIdx.x * 256 + threadIdx.x;
    if (i >= n4) return;
    float4 v = src[i];
    bf16 h0,l0,h1,l1,h2,l2,h3,l3;
    split_bf16(v.x, h0, l0); split_bf16(v.y, h1, l1);
    split_bf16(v.z, h2, l2); split_bf16(v.w, h3, l3);
    hi[i] = make_ushort4(__bfloat16_as_ushort(h0), __bfloat16_as_ushort(h1),
                         __bfloat16_as_ushort(h2), __bfloat16_as_ushort(h3));
    lo[i] = make_ushort4(__bfloat16_as_ushort(l0), __bfloat16_as_ushort(l1),
                         __bfloat16_as_ushort(l2), __bfloat16_as_ushort(l3));
}

// ---------------- layernorm (unbiased std) ----------------------------------
__device__ __forceinline__ float block_sum(float v, float* red) {
    __syncthreads();
    #pragma unroll
    for (int o = 16; o; o >>= 1) v += __shfl_xor_sync(0xffffffffu, v, o);
    int tid = threadIdx.x;
    if ((tid & 31) == 0) red[tid >> 5] = v;
    __syncthreads();
    if (tid == 0) {
        float t = 0.f;
        #pragma unroll
        for (int i = 0; i < 8; i++) t += red[i];
        red[0] = t;
    }
    __syncthreads();
    return red[0];
}

template<bool BF16OUT>
__global__ __launch_bounds__(256) void ln_kernel(
    const float* __restrict__ x, const float* __restrict__ ga,
    const float* __restrict__ gb, float* __restrict__ out,
    bf16* __restrict__ oh, bf16* __restrict__ ol)
{
    __shared__ float red[8];
    const int row = blockIdx.x;
    const int tid = threadIdx.x;
    const float4 v = reinterpret_cast<const float4*>(x + (size_t)row * D_MODEL)[tid];

    float s = v.x + v.y + v.z + v.w;
    const float mean = block_sum(s, red) * (1.0f / D_MODEL);

    float4 d = make_float4(v.x - mean, v.y - mean, v.z - mean, v.w - mean);
    float sq = d.x*d.x + d.y*d.y + d.z*d.z + d.w*d.w;
    const float var = block_sum(sq, red) * (1.0f / (D_MODEL - 1));
    const float rstd = rsqrtf(var);

    const float4 a = reinterpret_cast<const float4*>(ga)[tid];
    const float4 b = reinterpret_cast<const float4*>(gb)[tid];
    float4 o;
    o.x = d.x * rstd * a.x + b.x;
    o.y = d.y * rstd * a.y + b.y;
    o.z = d.z * rstd * a.z + b.z;
    o.w = d.w * rstd * a.w + b.w;
    if (BF16OUT) {
        bf16 h0,l0,h1,l1,h2,l2,h3,l3;
        split_bf16(o.x, h0, l0); split_bf16(o.y, h1, l1);
        split_bf16(o.z, h2, l2); split_bf16(o.w, h3, l3);
        const size_t idx = (size_t)row * (D_MODEL/4) + tid;
        reinterpret_cast<ushort4*>(oh)[idx] =
            make_ushort4(__bfloat16_as_ushort(h0), __bfloat16_as_ushort(h1),
                         __bfloat16_as_ushort(h2), __bfloat16_as_ushort(h3));
        reinterpret_cast<ushort4*>(ol)[idx] =
            make_ushort4(__bfloat16_as_ushort(l0), __bfloat16_as_ushort(l1),
                         __bfloat16_as_ushort(l2), __bfloat16_as_ushort(l3));
    } else {
        reinterpret_cast<float4*>(out + (size_t)row * D_MODEL)[tid] = o;
    }
}

// ---------------- mma.sync bf16x3-split GEMM --------------------------------
#define NSTG      3
#define ROWB      80
#define TILE_B    (128*ROWB)
#define STAGE_B   (4*TILE_B)
#define GEMM_SMEM (NSTG*STAGE_B)

template<bool RELU, bool HASB, bool HASR, bool BF16OUT>
__global__ __launch_bounds__(256) void gemm_tc(
    const bf16* __restrict__ Ah, const bf16* __restrict__ Al,
    const bf16* __restrict__ Wh, const bf16* __restrict__ Wl,
    const float* __restrict__ bias, const float* __restrict__ res,
    float* __restrict__ C, bf16* __restrict__ Ch, bf16* __restrict__ Cl,
    int M, int N, int K)
{
    extern __shared__ char smem[];
    const uint32_t sb = smem_u32(smem);
    const int tid  = threadIdx.x;
    const int bm   = blockIdx.y << 7;
    const int bn   = blockIdx.x << 7;
    const int w    = tid >> 5, lane = tid & 31;
    const int mblock = (w & 3) << 5;
    const int nblock = (w >> 2) << 6;

    const uint32_t aRowByte = (uint32_t)(mblock + (lane & 15)) * ROWB
                            + ((lane >> 4) & 1) * 16;
    const uint32_t bRowByte = (uint32_t)(nblock + ((lane >> 4) << 3) + (lane & 7)) * ROWB
                            + ((lane >> 3) & 1) * 16;

    float acc[2][8][4];
    #pragma unroll
    for (int i = 0; i < 2; i++)
        #pragma unroll
        for (int j = 0; j < 8; j++)
            #pragma unroll
            for (int t = 0; t < 4; t++) acc[i][j][t] = 0.f;

    auto load1 = [&](const bf16* __restrict__ src, int row0, uint32_t sbase, int kt) {
        #pragma unroll
        for (int i = 0; i < 2; i++) {
            const int ch = tid + (i << 8);
            const int r = ch >> 2, c = ch & 3;
            cpasync16(sbase + (uint32_t)r * ROWB + c * 16,
                      src + (size_t)(row0 + r) * K + (kt << 5) + (c << 3));
        }
    };
    auto load_stage = [&](int kt, int slot) {
        const uint32_t base = sb + slot * STAGE_B;
        load1(Ah, bm, base,            kt);
        load1(Al, bm, base + TILE_B,   kt);
        load1(Wh, bn, base + 2*TILE_B, kt);
        load1(Wl, bn, base + 3*TILE_B, kt);
    };

    const int NK = K >> 5;
    load_stage(0, 0); CP_COMMIT();
    load_stage(1, 1); CP_COMMIT();

    for (int kt = 0; kt < NK; ++kt) {
        CP_WAIT1();
        __syncthreads();

        const uint32_t st = sb + (kt % NSTG) * STAGE_B;
        const uint32_t aHi = st + aRowByte;
        const uint32_t aLo = aHi + TILE_B;
        const uint32_t bHi = st + 2*TILE_B + bRowByte;
        const uint32_t bLo = bHi + TILE_B;

        #pragma unroll
        for (int ks = 0; ks < 2; ++ks) {
            uint32_t ah[2][4], al[2][4], bh[4][4], bl[4][4];
            #pragma unroll
            for (int mt = 0; mt < 2; mt++) {
                ldm4(ah[mt], aHi + mt*(16*ROWB) + ks*32);
                ldm4(al[mt], aLo + mt*(16*ROWB) + ks*32);
            }
            #pragma unroll
            for (int np = 0; np < 4; np++) {
                ldm4(bh[np], bHi + np*(16*ROWB) + ks*32);
                ldm4(bl[np], bLo + np*(16*ROWB) + ks*32);
            }
            #pragma unroll
            for (int mt = 0; mt < 2; mt++)
                #pragma unroll
                for (int np = 0; np < 4; np++)
                    #pragma unroll
                    for (int h = 0; h < 2; h++) {
                        float* c = acc[mt][np*2 + h];
                        mma16816(c, ah[mt], bh[np][h*2], bh[np][h*2+1]);
                        mma16816(c, ah[mt], bl[np][h*2], bl[np][h*2+1]);
                        mma16816(c, al[mt], bh[np][h*2], bh[np][h*2+1]);
                    }
        }
        __syncthreads();

        const int nt = kt + 2;
        if (nt < NK) load_stage(nt, nt % NSTG);
        CP_COMMIT();
    }

    #pragma unroll
    for (int mt = 0; mt < 2; mt++) {
        #pragma unroll
        for (int nt = 0; nt < 8; nt++) {
            const int r0 = bm + mblock + mt*16 + (lane >> 2);
            const int c0 = bn + nblock + nt*8 + ((lane & 3) << 1);
            float v00 = acc[mt][nt][0], v01 = acc[mt][nt][1];
            float v10 = acc[mt][nt][2], v11 = acc[mt][nt][3];
            if (HASB) {
                const float2 bb = *(const float2*)(bias + c0);
                v00 += bb.x; v01 += bb.y; v10 += bb.x; v11 += bb.y;
            }
            if (RELU) {
                v00 = fmaxf(v00, 0.f); v01 = fmaxf(v01, 0.f);
                v10 = fmaxf(v10, 0.f); v11 = fmaxf(v11, 0.f);
            }
            const size_t o0 = (size_t)r0 * N + c0;
            const size_t o1 = o0 + (size_t)8 * N;
            if (HASR) {
                const float2 r4a = *(const float2*)(res + o0);
                const float2 r4b = *(const float2*)(res + o1);
                v00 += r4a.x; v01 += r4a.y; v10 += r4b.x; v11 += r4b.y;
            }
            if (BF16OUT) {
                bf16 h0,l0,h1,l1;
                split_bf16(v00, h0, l0); split_bf16(v01, h1, l1);
                *(ushort2*)(Ch + o0) = make_ushort2(__bfloat16_as_ushort(h0),
                                                    __bfloat16_as_ushort(h1));
                *(ushort2*)(Cl + o0) = make_ushort2(__bfloat16_as_ushort(l0),
                                                    __bfloat16_as_ushort(l1));
                split_bf16(v10, h0, l0); split_bf16(v11, h1, l1);
                *(ushort2*)(Ch + o1) = make_ushort2(__bfloat16_as_ushort(h0),
                                                    __bfloat16_as_ushort(h1));
                *(ushort2*)(Cl + o1) = make_ushort2(__bfloat16_as_ushort(l0),
                                                    __bfloat16_as_ushort(l1));
            } else {
                *(float2*)(C + o0) = make_float2(v00, v01);
                *(float2*)(C + o1) = make_float2(v10, v11);
            }
        }
    }
}

// ---------------- tensor-core flash attention --------------------------------
// CTA: 64 q-rows x one head. 4 warps, 16 q-rows each. K/V blocks of 64 keys,
// double-buffered cp.async. S and PV via bf16 hi/lo 3-pass mma.sync.
#define AROWB 144                 // 64 bf16 dims (128B) + 16B pad
#define ATILE (64*AROWB)          // 9216 B
#define ASTG  (4*ATILE)           // Kh,Kl,Vh,Vl
#define SM_KV (2*ATILE)           // after Qh,Ql
#define SM_MASK (SM_KV + 2*ASTG)
#define ATTN_SMEM (SM_MASK + 512)

__global__ __launch_bounds__(128) void attn_tc(
    const bf16* __restrict__ Qh_, const bf16* __restrict__ Ql_,
    const bf16* __restrict__ Kh_, const bf16* __restrict__ Kl_,
    const bf16* __restrict__ Vh_, const bf16* __restrict__ Vl_,
    const int* __restrict__ mask,
    bf16* __restrict__ Oh, bf16* __restrict__ Ol)
{
    extern __shared__ char smem[];
    const uint32_t sb = smem_u32(smem);
    const int tid = threadIdx.x, w = tid >> 5, lane = tid & 31;
    const int q0 = blockIdx.x << 6;
    const int h  = blockIdx.y, b = blockIdx.z;
    const size_t hoff = (size_t)h * DKH;
    const int g = lane >> 2, t4 = lane & 3;

    auto loadQ = [&](const bf16* __restrict__ src, uint32_t base) {
        #pragma unroll
        for (int i = 0; i < 4; i++) {
            const int ch = tid + (i << 7);
            const int r = ch >> 3, c = ch & 7;
            cpasync16(base + (uint32_t)r * AROWB + c * 16,
                      src + (size_t)(b * SEQ + q0 + r) * D_MODEL + hoff + (c << 3));
        }
    };
    auto loadKV = [&](int blk, int slot) {
        const uint32_t base = sb + SM_KV + slot * ASTG;
        const bf16* srcs[4] = {Kh_, Kl_, Vh_, Vl_};
        #pragma unroll
        for (int tI = 0; tI < 4; tI++) {
            #pragma unroll
            for (int i = 0; i < 4; i++) {
                const int ch = tid + (i << 7);
                const int r = ch >> 3, c = ch & 7;
                cpasync16(base + tI * ATILE + (uint32_t)r * AROWB + c * 16,
                          srcs[tI] + (size_t)(b * SEQ + (blk << 6) + r) * D_MODEL
                                   + hoff + (c << 3));
            }
        }
        if (tid < 16)
            cpasync16(sb + SM_MASK + slot * 256 + tid * 16,
                      mask + (size_t)b * SEQ + (blk << 6) + tid * 4);
    };

    loadQ(Qh_, sb);
    loadQ(Ql_, sb + ATILE);
    loadKV(0, 0);
    CP_COMMIT();

    uint32_t qh[4][4], ql[4][4];
    float o[8][4];
    #pragma unroll
    for (int i = 0; i < 8; i++)
        #pragma unroll
        for (int j = 0; j < 4; j++) o[i][j] = 0.f;
    float m0 = -INFINITY, m1 = -INFINITY, l0 = 0.f, l1 = 0.f;

    const uint32_t aoff = (uint32_t)((w * 16 + (lane & 15)) * AROWB)
                        + (((lane >> 4) & 1) << 4);
    const uint32_t boff = (uint32_t)((((lane >> 4) << 3) + (lane & 7)) * AROWB)
                        + (((lane >> 3) & 1) << 4);
    const uint32_t voff = (uint32_t)((lane & 15) * AROWB) + ((lane >> 4) << 4);

    const int NB = SEQ / 64;
    for (int it = 0; it < NB; ++it) {
        if (it + 1 < NB) { loadKV(it + 1, (it + 1) & 1); CP_COMMIT(); CP_WAIT1(); }
        else             { CP_WAIT0(); }
        __syncthreads();

        if (it == 0) {
            #pragma unroll
            for (int ks = 0; ks < 4; ks++) {
                ldm4(qh[ks], sb + aoff + ks * 32);
                ldm4(ql[ks], sb + ATILE + aoff + ks * 32);
            }
        }

        const uint32_t stg = sb + SM_KV + (it & 1) * ASTG;
        const int* msk = (const int*)(smem + SM_MASK + (it & 1) * 256);

        // ---- S = Q @ K^T (3-pass hi/lo) ----
        float sa[8][4];
        #pragma unroll
        for (int i = 0; i < 8; i++)
            #pragma unroll
            for (int j = 0; j < 4; j++) sa[i][j] = 0.f;

        #pragma unroll
        for (int ks = 0; ks < 4; ks++) {
            #pragma unroll
            for (int ng = 0; ng < 4; ng++) {
                uint32_t kh4[4], kl4[4];
                const uint32_t ad = stg + boff + ng * (16 * AROWB) + ks * 32;
                ldm4(kh4, ad);
                ldm4(kl4, ad + ATILE);
                float* c0 = sa[2*ng];
                float* c1 = sa[2*ng + 1];
                mma16816(c0, qh[ks], kh4[0], kh4[1]);
                mma16816(c1, qh[ks], kh4[2], kh4[3]);
                mma16816(c0, qh[ks], kl4[0], kl4[1]);
                mma16816(c1, qh[ks], kl4[2], kl4[3]);
                mma16816(c0, ql[ks], kh4[0], kh4[1]);
                mma16816(c1, ql[ks], kh4[2], kh4[3]);
            }
        }

        // ---- mask + scale ----
        #pragma unroll
        for (int nt = 0; nt < 8; nt++) {
            const int j0 = nt * 8 + (t4 << 1);
            const bool k0m = msk[j0] != 0, k1m = msk[j0 + 1] != 0;
            sa[nt][0] = k0m ? -1e9f : sa[nt][0] * 0.125f;
            sa[nt][1] = k1m ? -1e9f : sa[nt][1] * 0.125f;
            sa[nt][2] = k0m ? -1e9f : sa[nt][2] * 0.125f;
            sa[nt][3] = k1m ? -1e9f : sa[nt][3] * 0.125f;
        }

        // ---- online softmax (fp32, quad-shuffle row reductions) ----
        float mx0 = -INFINITY, mx1 = -INFINITY;
        #pragma unroll
        for (int nt = 0; nt < 8; nt++) {
            mx0 = fmaxf(mx0, fmaxf(sa[nt][0], sa[nt][1]));
            mx1 = fmaxf(mx1, fmaxf(sa[nt][2], sa[nt][3]));
        }
        mx0 = fmaxf(mx0, __shfl_xor_sync(0xffffffffu, mx0, 1));
        mx0 = fmaxf(mx0, __shfl_xor_sync(0xffffffffu, mx0, 2));
        mx1 = fmaxf(mx1, __shfl_xor_sync(0xffffffffu, mx1, 1));
        mx1 = fmaxf(mx1, __shfl_xor_sync(0xffffffffu, mx1, 2));
        const float nm0 = fmaxf(m0, mx0), nm1 = fmaxf(m1, mx1);
        const float f0 = __expf(m0 - nm0), f1 = __expf(m1 - nm1);

        float s0 = 0.f, s1 = 0.f;
        #pragma unroll
        for (int nt = 0; nt < 8; nt++) {
            sa[nt][0] = __expf(sa[nt][0] - nm0);
            sa[nt][1] = __expf(sa[nt][1] - nm0);
            sa[nt][2] = __expf(sa[nt][2] - nm1);
            sa[nt][3] = __expf(sa[nt][3] - nm1);
            s0 += sa[nt][0] + sa[nt][1];
            s1 += sa[nt][2] + sa[nt][3];
        }
        s0 += __shfl_xor_sync(0xffffffffu, s0, 1);
        s0 += __shfl_xor_sync(0xffffffffu, s0, 2);
        s1 += __shfl_xor_sync(0xffffffffu, s1, 1);
        s1 += __shfl_xor_sync(0xffffffffu, s1, 2);
        m0 = nm0; m1 = nm1;
        l0 = l0 * f0 + s0;
        l1 = l1 * f1 + s1;
        #pragma unroll
        for (int d = 0; d < 8; d++) {
            o[d][0] *= f0; o[d][1] *= f0;
            o[d][2] *= f1; o[d][3] *= f1;
        }

        // ---- repack P (accum layout -> a-frag layout), hi/lo split ----
        uint32_t pah[4][4], pal[4][4];
        #pragma unroll
        for (int ks = 0; ks < 4; ks++) {
            #pragma unroll
            for (int half = 0; half < 2; half++) {       // tiles 2ks, 2ks+1
                const float* sv = sa[2*ks + half];
                bf16 h0,lo0,h1,lo1,h2,lo2,h3,lo3;
                split_bf16(sv[0], h0, lo0); split_bf16(sv[1], h1, lo1);
                split_bf16(sv[2], h2, lo2); split_bf16(sv[3], h3, lo3);
                pah[ks][half*2 + 0] = packbf(h0, h1);    // row g
                pah[ks][half*2 + 1] = packbf(h2, h3);    // row g+8
                pal[ks][half*2 + 0] = packbf(lo0, lo1);
                pal[ks][half*2 + 1] = packbf(lo2, lo3);
            }
        }

        // ---- O += P @ V (3-pass hi/lo) ----
        #pragma unroll
        for (int ks = 0; ks < 4; ks++) {
            #pragma unroll
            for (int dg = 0; dg < 4; dg++) {
                uint32_t vh4[4], vl4[4];
                const uint32_t ad = stg + 2*ATILE + voff
                                  + ks * (16 * AROWB) + dg * 32;
                ldm4t(vh4, ad);
                ldm4t(vl4, ad + ATILE);
                float* c0 = o[2*dg];
                float* c1 = o[2*dg + 1];
                mma16816(c0, pah[ks], vh4[0], vh4[1]);
                mma16816(c1, pah[ks], vh4[2], vh4[3]);
                mma16816(c0, pah[ks], vl4[0], vl4[1]);
                mma16816(c1, pah[ks], vl4[2], vl4[3]);
                mma16816(c0, pal[ks], vh4[0], vh4[1]);
                mma16816(c1, pal[ks], vh4[2], vh4[3]);
            }
        }
        __syncthreads();
    }

    // ---- epilogue: normalize, split hi/lo, store ----
    const float i0 = 1.f / l0, i1 = 1.f / l1;
    const size_t r0 = (size_t)(b * SEQ + q0 + w * 16 + g) * D_MODEL + hoff;
    const size_t r1 = r0 + (size_t)8 * D_MODEL;
    #pragma unroll
    for (int d = 0; d < 8; d++) {
        const int col = d * 8 + (t4 << 1);
        bf16 h0,lo0,h1,lo1;
        split_bf16(o[d][0] * i0, h0, lo0);
        split_bf16(o[d][1] * i0, h1, lo1);
        *(ushort2*)(Oh + r0 + col) = make_ushort2(__bfloat16_as_ushort(h0),
                                                  __bfloat16_as_ushort(h1));
        *(ushort2*)(Ol + r0 + col) = make_ushort2(__bfloat16_as_ushort(lo0),
                                                  __bfloat16_as_ushort(lo1));
        split_bf16(o[d][2] * i1, h0, lo0);
        split_bf16(o[d][3] * i1, h1, lo1);
        *(ushort2*)(Oh + r1 + col) = make_ushort2(__bfloat16_as_ushort(h0),
                                                  __bfloat16_as_ushort(h1));
        *(ushort2*)(Ol + r1 + col) = make_ushort2(__bfloat16_as_ushort(lo0),
                                                  __bfloat16_as_ushort(lo1));
    }
}

// ---------------- launch -----------------------------------------------------
extern "C" void kernel_launch(void* const* d_in, const int* in_sizes, int n_in,
                              void* d_out, int out_size)
{
    const float* x     = (const float*)d_in[0];
    const float* w_q   = (const float*)d_in[1];
    const float* w_k   = (const float*)d_in[2];
    const float* w_v   = (const float*)d_in[3];
    const float* w_o   = (const float*)d_in[4];
    const float* l1_w  = (const float*)d_in[5];
    const float* l1_b  = (const float*)d_in[6];
    const float* l2_w  = (const float*)d_in[7];
    const float* l2_b  = (const float*)d_in[8];
    const float* n1a   = (const float*)d_in[9];
    const float* n1b   = (const float*)d_in[10];
    const float* n2a   = (const float*)d_in[11];
    const float* n2b   = (const float*)d_in[12];
    const float* nfa   = (const float*)d_in[13];
    const float* nfb   = (const float*)d_in[14];
    const int*   mask  = (const int*)d_in[15];
    float* out = (float*)d_out;

    float *x1, *x2;
    bf16 *xnh,*xnl,*qh_,*ql_,*kh_,*kl_,*vh_,*vl_,*hh,*hl,*aoh,*aol,*ffh,*ffl;
    bf16 *wqh,*wql,*wkh,*wkl,*wvh,*wvl,*woh,*wol,*l1h,*l1l,*l2h,*l2l;
    cudaGetSymbolAddress((void**)&x1, g_x1);
    cudaGetSymbolAddress((void**)&x2, g_x2);
    cudaGetSymbolAddress((void**)&xnh, g_xnh); cudaGetSymbolAddress((void**)&xnl, g_xnl);
    cudaGetSymbolAddress((void**)&qh_, g_qh);  cudaGetSymbolAddress((void**)&ql_, g_ql);
    cudaGetSymbolAddress((void**)&kh_, g_kh);  cudaGetSymbolAddress((void**)&kl_, g_kl);
    cudaGetSymbolAddress((void**)&vh_, g_vh);  cudaGetSymbolAddress((void**)&vl_, g_vl);
    cudaGetSymbolAddress((void**)&hh,  g_hh);  cudaGetSymbolAddress((void**)&hl,  g_hl);
    cudaGetSymbolAddress((void**)&aoh, g_aoh); cudaGetSymbolAddress((void**)&aol, g_aol);
    cudaGetSymbolAddress((void**)&ffh, g_ffh); cudaGetSymbolAddress((void**)&ffl, g_ffl);
    cudaGetSymbolAddress((void**)&wqh, g_wqh); cudaGetSymbolAddress((void**)&wql, g_wql);
    cudaGetSymbolAddress((void**)&wkh, g_wkh); cudaGetSymbolAddress((void**)&wkl, g_wkl);
    cudaGetSymbolAddress((void**)&wvh, g_wvh); cudaGetSymbolAddress((void**)&wvl, g_wvl);
    cudaGetSymbolAddress((void**)&woh, g_woh); cudaGetSymbolAddress((void**)&wol, g_wol);
    cudaGetSymbolAddress((void**)&l1h, g_l1h); cudaGetSymbolAddress((void**)&l1l, g_l1l);
    cudaGetSymbolAddress((void**)&l2h, g_l2h); cudaGetSymbolAddress((void**)&l2l, g_l2l);

    cudaFuncSetAttribute(gemm_tc<false,false,false,true>,
        cudaFuncAttributeMaxDynamicSharedMemorySize, GEMM_SMEM);
    cudaFuncSetAttribute(gemm_tc<false,false,true,false>,
        cudaFuncAttributeMaxDynamicSharedMemorySize, GEMM_SMEM);
    cudaFuncSetAttribute(gemm_tc<true,true,false,true>,
        cudaFuncAttributeMaxDynamicSharedMemorySize, GEMM_SMEM);
    cudaFuncSetAttribute(gemm_tc<false,true,true,false>,
        cudaFuncAttributeMaxDynamicSharedMemorySize, GEMM_SMEM);
    cudaFuncSetAttribute(attn_tc,
        cudaFuncAttributeMaxDynamicSharedMemorySize, ATTN_SMEM);

    const int nDD4 = D_MODEL*D_MODEL/4, nFD4 = D_FF*D_MODEL/4;
    cvt_kernel<<<(nDD4+255)/256, 256>>>((const float4*)w_q,  (ushort4*)wqh, (ushort4*)wql, nDD4);
    cvt_kernel<<<(nDD4+255)/256, 256>>>((const float4*)w_k,  (ushort4*)wkh, (ushort4*)wkl, nDD4);
    cvt_kernel<<<(nDD4+255)/256, 256>>>((const float4*)w_v,  (ushort4*)wvh, (ushort4*)wvl, nDD4);
    cvt_kernel<<<(nDD4+255)/256, 256>>>((const float4*)w_o,  (ushort4*)woh, (ushort4*)wol, nDD4);
    cvt_kernel<<<(nFD4+255)/256, 256>>>((const float4*)l1_w, (ushort4*)l1h, (ushort4*)l1l, nFD4);
    cvt_kernel<<<(nFD4+255)/256, 256>>>((const float4*)l2_w, (ushort4*)l2h, (ushort4*)l2l, nFD4);

    const dim3 gD(D_MODEL/128, NROWS/128);
    const dim3 gF(D_FF/128,    NROWS/128);

    // 1) xn = LN1(x) -> bf16 hi/lo
    ln_kernel<true><<<NROWS, 256>>>(x, n1a, n1b, nullptr, xnh, xnl);
    // 2) Q,K,V -> bf16 hi/lo directly
    gemm_tc<false,false,false,true><<<gD, 256, GEMM_SMEM>>>(
        xnh, xnl, wqh, wql, nullptr, nullptr, nullptr, qh_, ql_, NROWS, D_MODEL, D_MODEL);
    gemm_tc<false,false,false,true><<<gD, 256, GEMM_SMEM>>>(
        xnh, xnl, wkh, wkl, nullptr, nullptr, nullptr, kh_, kl_, NROWS, D_MODEL, D_MODEL);
    gemm_tc<false,false,false,true><<<gD, 256, GEMM_SMEM>>>(
        xnh, xnl, wvh, wvl, nullptr, nullptr, nullptr, vh_, vl_, NROWS, D_MODEL, D_MODEL);
    // 3) attention (tensor cores) -> bf16 hi/lo
    attn_tc<<<dim3(SEQ/64, NH, BATCH), 128, ATTN_SMEM>>>(
        qh_, ql_, kh_, kl_, vh_, vl_, mask, aoh, aol);
    // 4) x1 = x + ao @ w_o^T (fp32)
    gemm_tc<false,false,true,false><<<gD, 256, GEMM_SMEM>>>(
        aoh, aol, woh, wol, nullptr, x, x1, nullptr, nullptr, NROWS, D_MODEL, D_MODEL);
    // 5) h = LN2(x1) -> bf16 hi/lo
    ln_kernel<true><<<NROWS, 256>>>(x1, n2a, n2b, nullptr, hh, hl);
    // 6) ff = relu(h @ l1^T + b1) -> bf16 hi/lo
    gemm_tc<true,true,false,true><<<gF, 256, GEMM_SMEM>>>(
        hh, hl, l1h, l1l, l1_b, nullptr, nullptr, ffh, ffl, NROWS, D_FF, D_MODEL);
    // 7) x2 = x1 + ff @ l2^T + b2 (fp32)
    gemm_tc<false,true,true,false><<<gD, 256, GEMM_SMEM>>>(
        ffh, ffl, l2h, l2l, l2_b, x1, x2, nullptr, nullptr, NROWS, D_MODEL, D_FF);
    // 8) out = LNf(x2)
    ln_kernel<false><<<NROWS, 256>>>(x2, nfa, nfb, out, nullptr, nullptr);
}

// round 6
// speedup vs baseline: 3.4290x; 1.1453x over previous
#include <cuda_runtime.h>
#include <cuda_bf16.h>
#include <math.h>
#include <stdint.h>

#define D_MODEL 1024
#define NH      16
#define DKH     64
#define D_FF    4096
#define BATCH   4
#define SEQ     2048
#define NROWS   (BATCH*SEQ)
#define QKVN    3072
#define QKVLD   3072

typedef __nv_bfloat16 bf16;

// ---------------- scratch (device globals; no runtime allocation) ----------
__device__ float g_x1[NROWS * D_MODEL];
__device__ float g_x2[NROWS * D_MODEL];

__device__ bf16 g_xnh[NROWS * D_MODEL], g_xnl[NROWS * D_MODEL];
__device__ bf16 g_qkvh[(size_t)NROWS * QKVN], g_qkvl[(size_t)NROWS * QKVN];
__device__ bf16 g_hh [NROWS * D_MODEL], g_hl [NROWS * D_MODEL];
__device__ bf16 g_aoh[NROWS * D_MODEL], g_aol[NROWS * D_MODEL];
__device__ bf16 g_ffh[(size_t)NROWS * D_FF], g_ffl[(size_t)NROWS * D_FF];

__device__ bf16 g_wqkvh[QKVN*D_MODEL], g_wqkvl[QKVN*D_MODEL];
__device__ bf16 g_woh[D_MODEL*D_MODEL], g_wol[D_MODEL*D_MODEL];
__device__ bf16 g_l1h[D_FF*D_MODEL],   g_l1l[D_FF*D_MODEL];
__device__ bf16 g_l2h[D_MODEL*D_FF],   g_l2l[D_MODEL*D_FF];

// ---------------- small PTX helpers ----------------------------------------
__device__ __forceinline__ uint32_t smem_u32(const void* p) {
    uint32_t a;
    asm("{ .reg .u64 t; cvta.to.shared.u64 t, %1; cvt.u32.u64 %0, t; }"
        : "=r"(a) : "l"(p));
    return a;
}
__device__ __forceinline__ void cpasync16(uint32_t dst, const void* src) {
    asm volatile("cp.async.cg.shared.global [%0], [%1], 16;"
                 :: "r"(dst), "l"(src));
}
#define CP_COMMIT() asm volatile("cp.async.commit_group;" ::: "memory")
#define CP_WAIT1()  asm volatile("cp.async.wait_group 1;" ::: "memory")
#define CP_WAIT0()  asm volatile("cp.async.wait_group 0;" ::: "memory")

__device__ __forceinline__ void ldm4(uint32_t* r, uint32_t addr) {
    asm volatile("ldmatrix.sync.aligned.m8n8.x4.shared.b16 {%0,%1,%2,%3}, [%4];"
        : "=r"(r[0]), "=r"(r[1]), "=r"(r[2]), "=r"(r[3]) : "r"(addr));
}
__device__ __forceinline__ void ldm4t(uint32_t* r, uint32_t addr) {
    asm volatile("ldmatrix.sync.aligned.m8n8.x4.trans.shared.b16 {%0,%1,%2,%3}, [%4];"
        : "=r"(r[0]), "=r"(r[1]), "=r"(r[2]), "=r"(r[3]) : "r"(addr));
}
__device__ __forceinline__ void mma16816(float* c, const uint32_t* a,
                                         uint32_t b0, uint32_t b1) {
    asm volatile("mma.sync.aligned.m16n8k16.row.col.f32.bf16.bf16.f32 "
        "{%0,%1,%2,%3}, {%4,%5,%6,%7}, {%8,%9}, {%0,%1,%2,%3};"
        : "+f"(c[0]), "+f"(c[1]), "+f"(c[2]), "+f"(c[3])
        : "r"(a[0]), "r"(a[1]), "r"(a[2]), "r"(a[3]), "r"(b0), "r"(b1));
}

__device__ __forceinline__ void split_bf16(float f, bf16& h, bf16& l) {
    h = __float2bfloat16_rn(f);
    l = __float2bfloat16_rn(f - __bfloat162float(h));
}
__device__ __forceinline__ uint32_t packbf(bf16 a, bf16 b) {
    return (uint32_t)__bfloat16_as_ushort(a) |
           ((uint32_t)__bfloat16_as_ushort(b) << 16);
}

// ---------------- weight fp32 -> bf16 hi/lo conversion ----------------------
__global__ __launch_bounds__(256) void cvt_kernel(
    const float4* __restrict__ src, ushort4* __restrict__ hi,
    ushort4* __restrict__ lo, int n4)
{
    int i = blockIdx.x * 256 + threadIdx.x;
    if (i >= n4) return;
    float4 v = src[i];
    bf16 h0,l0,h1,l1,h2,l2,h3,l3;
    split_bf16(v.x, h0, l0); split_bf16(v.y, h1, l1);
    split_bf16(v.z, h2, l2); split_bf16(v.w, h3, l3);
    hi[i] = make_ushort4(__bfloat16_as_ushort(h0), __bfloat16_as_ushort(h1),
                         __bfloat16_as_ushort(h2), __bfloat16_as_ushort(h3));
    lo[i] = make_ushort4(__bfloat16_as_ushort(l0), __bfloat16_as_ushort(l1),
                         __bfloat16_as_ushort(l2), __bfloat16_as_ushort(l3));
}

// ---------------- layernorm (unbiased std) ----------------------------------
__device__ __forceinline__ float block_sum(float v, float* red) {
    __syncthreads();
    #pragma unroll
    for (int o = 16; o; o >>= 1) v += __shfl_xor_sync(0xffffffffu, v, o);
    int tid = threadIdx.x;
    if ((tid & 31) == 0) red[tid >> 5] = v;
    __syncthreads();
    if (tid == 0) {
        float t = 0.f;
        #pragma unroll
        for (int i = 0; i < 8; i++) t += red[i];
        red[0] = t;
    }
    __syncthreads();
    return red[0];
}

template<bool BF16OUT>
__global__ __launch_bounds__(256) void ln_kernel(
    const float* __restrict__ x, const float* __restrict__ ga,
    const float* __restrict__ gb, float* __restrict__ out,
    bf16* __restrict__ oh, bf16* __restrict__ ol)
{
    __shared__ float red[8];
    const int row = blockIdx.x;
    const int tid = threadIdx.x;
    const float4 v = reinterpret_cast<const float4*>(x + (size_t)row * D_MODEL)[tid];

    float s = v.x + v.y + v.z + v.w;
    const float mean = block_sum(s, red) * (1.0f / D_MODEL);

    float4 d = make_float4(v.x - mean, v.y - mean, v.z - mean, v.w - mean);
    float sq = d.x*d.x + d.y*d.y + d.z*d.z + d.w*d.w;
    const float var = block_sum(sq, red) * (1.0f / (D_MODEL - 1));
    const float rstd = rsqrtf(var);

    const float4 a = reinterpret_cast<const float4*>(ga)[tid];
    const float4 b = reinterpret_cast<const float4*>(gb)[tid];
    float4 o;
    o.x = d.x * rstd * a.x + b.x;
    o.y = d.y * rstd * a.y + b.y;
    o.z = d.z * rstd * a.z + b.z;
    o.w = d.w * rstd * a.w + b.w;
    if (BF16OUT) {
        bf16 h0,l0,h1,l1,h2,l2,h3,l3;
        split_bf16(o.x, h0, l0); split_bf16(o.y, h1, l1);
        split_bf16(o.z, h2, l2); split_bf16(o.w, h3, l3);
        const size_t idx = (size_t)row * (D_MODEL/4) + tid;
        reinterpret_cast<ushort4*>(oh)[idx] =
            make_ushort4(__bfloat16_as_ushort(h0), __bfloat16_as_ushort(h1),
                         __bfloat16_as_ushort(h2), __bfloat16_as_ushort(h3));
        reinterpret_cast<ushort4*>(ol)[idx] =
            make_ushort4(__bfloat16_as_ushort(l0), __bfloat16_as_ushort(l1),
                         __bfloat16_as_ushort(l2), __bfloat16_as_ushort(l3));
    } else {
        reinterpret_cast<float4*>(out + (size_t)row * D_MODEL)[tid] = o;
    }
}

// ---------------- mma.sync bf16x3-split GEMM --------------------------------
// BM=BN=128, BK=32, 2-stage cp.async pipeline, 2 CTAs/SM.
#define NSTG      2
#define ROWB      80
#define TILE_B    (128*ROWB)
#define STAGE_B   (4*TILE_B)
#define GEMM_SMEM (NSTG*STAGE_B)   // 81920 B

template<bool RELU, bool HASB, bool HASR, bool BF16OUT>
__global__ __launch_bounds__(256, 2) void gemm_tc(
    const bf16* __restrict__ Ah, const bf16* __restrict__ Al,
    const bf16* __restrict__ Wh, const bf16* __restrict__ Wl,
    const float* __restrict__ bias, const float* __restrict__ res,
    float* __restrict__ C, bf16* __restrict__ Ch, bf16* __restrict__ Cl,
    int M, int N, int K)
{
    extern __shared__ char smem[];
    const uint32_t sb = smem_u32(smem);
    const int tid  = threadIdx.x;
    const int bm   = blockIdx.y << 7;
    const int bn   = blockIdx.x << 7;
    const int w    = tid >> 5, lane = tid & 31;
    const int mblock = (w & 3) << 5;
    const int nblock = (w >> 2) << 6;

    const uint32_t aRowByte = (uint32_t)(mblock + (lane & 15)) * ROWB
                            + ((lane >> 4) & 1) * 16;
    const uint32_t bRowByte = (uint32_t)(nblock + ((lane >> 4) << 3) + (lane & 7)) * ROWB
                            + ((lane >> 3) & 1) * 16;

    float acc[2][8][4];
    #pragma unroll
    for (int i = 0; i < 2; i++)
        #pragma unroll
        for (int j = 0; j < 8; j++)
            #pragma unroll
            for (int t = 0; t < 4; t++) acc[i][j][t] = 0.f;

    auto load1 = [&](const bf16* __restrict__ src, int row0, uint32_t sbase, int kt) {
        #pragma unroll
        for (int i = 0; i < 2; i++) {
            const int ch = tid + (i << 8);
            const int r = ch >> 2, c = ch & 3;
            cpasync16(sbase + (uint32_t)r * ROWB + c * 16,
                      src + (size_t)(row0 + r) * K + (kt << 5) + (c << 3));
        }
    };
    auto load_stage = [&](int kt, int slot) {
        const uint32_t base = sb + slot * STAGE_B;
        load1(Ah, bm, base,            kt);
        load1(Al, bm, base + TILE_B,   kt);
        load1(Wh, bn, base + 2*TILE_B, kt);
        load1(Wl, bn, base + 3*TILE_B, kt);
    };

    const int NK = K >> 5;
    load_stage(0, 0); CP_COMMIT();
    load_stage(1, 1); CP_COMMIT();

    for (int kt = 0; kt < NK; ++kt) {
        CP_WAIT1();
        __syncthreads();

        const uint32_t st = sb + (kt & 1) * STAGE_B;
        const uint32_t aHi = st + aRowByte;
        const uint32_t aLo = aHi + TILE_B;
        const uint32_t bHi = st + 2*TILE_B + bRowByte;
        const uint32_t bLo = bHi + TILE_B;

        #pragma unroll
        for (int ks = 0; ks < 2; ++ks) {
            uint32_t ah[2][4], al[2][4];
            #pragma unroll
            for (int mt = 0; mt < 2; mt++) {
                ldm4(ah[mt], aHi + mt*(16*ROWB) + ks*32);
                ldm4(al[mt], aLo + mt*(16*ROWB) + ks*32);
            }
            #pragma unroll
            for (int np = 0; np < 4; np++) {
                uint32_t bh4[4], bl4[4];
                ldm4(bh4, bHi + np*(16*ROWB) + ks*32);
                ldm4(bl4, bLo + np*(16*ROWB) + ks*32);
                #pragma unroll
                for (int mt = 0; mt < 2; mt++)
                    #pragma unroll
                    for (int h = 0; h < 2; h++) {
                        float* c = acc[mt][np*2 + h];
                        mma16816(c, ah[mt], bh4[h*2], bh4[h*2+1]);
                        mma16816(c, ah[mt], bl4[h*2], bl4[h*2+1]);
                        mma16816(c, al[mt], bh4[h*2], bh4[h*2+1]);
                    }
            }
        }
        __syncthreads();

        const int nt = kt + 2;
        if (nt < NK) load_stage(nt, kt & 1);
        CP_COMMIT();
    }

    #pragma unroll
    for (int mt = 0; mt < 2; mt++) {
        #pragma unroll
        for (int nt = 0; nt < 8; nt++) {
            const int r0 = bm + mblock + mt*16 + (lane >> 2);
            const int c0 = bn + nblock + nt*8 + ((lane & 3) << 1);
            float v00 = acc[mt][nt][0], v01 = acc[mt][nt][1];
            float v10 = acc[mt][nt][2], v11 = acc[mt][nt][3];
            if (HASB) {
                const float2 bb = *(const float2*)(bias + c0);
                v00 += bb.x; v01 += bb.y; v10 += bb.x; v11 += bb.y;
            }
            if (RELU) {
                v00 = fmaxf(v00, 0.f); v01 = fmaxf(v01, 0.f);
                v10 = fmaxf(v10, 0.f); v11 = fmaxf(v11, 0.f);
            }
            const size_t o0 = (size_t)r0 * N + c0;
            const size_t o1 = o0 + (size_t)8 * N;
            if (HASR) {
                const float2 r4a = *(const float2*)(res + o0);
                const float2 r4b = *(const float2*)(res + o1);
                v00 += r4a.x; v01 += r4a.y; v10 += r4b.x; v11 += r4b.y;
            }
            if (BF16OUT) {
                bf16 h0,l0,h1,l1;
                split_bf16(v00, h0, l0); split_bf16(v01, h1, l1);
                *(ushort2*)(Ch + o0) = make_ushort2(__bfloat16_as_ushort(h0),
                                                    __bfloat16_as_ushort(h1));
                *(ushort2*)(Cl + o0) = make_ushort2(__bfloat16_as_ushort(l0),
                                                    __bfloat16_as_ushort(l1));
                split_bf16(v10, h0, l0); split_bf16(v11, h1, l1);
                *(ushort2*)(Ch + o1) = make_ushort2(__bfloat16_as_ushort(h0),
                                                    __bfloat16_as_ushort(h1));
                *(ushort2*)(Cl + o1) = make_ushort2(__bfloat16_as_ushort(l0),
                                                    __bfloat16_as_ushort(l1));
            } else {
                *(float2*)(C + o0) = make_float2(v00, v01);
                *(float2*)(C + o1) = make_float2(v10, v11);
            }
        }
    }
}

// ---------------- tensor-core flash attention --------------------------------
// Q/K/V read from the fused [rows, 3072] hi/lo buffers (stride QKVLD).
#define AROWB 144
#define ATILE (64*AROWB)
#define ASTG  (4*ATILE)
#define SM_KV (2*ATILE)
#define SM_MASK (SM_KV + 2*ASTG)
#define ATTN_SMEM (SM_MASK + 512)

__global__ __launch_bounds__(128) void attn_tc(
    const bf16* __restrict__ QKVh, const bf16* __restrict__ QKVl,
    const int* __restrict__ mask,
    bf16* __restrict__ Oh, bf16* __restrict__ Ol)
{
    extern __shared__ char smem[];
    const uint32_t sb = smem_u32(smem);
    const int tid = threadIdx.x, w = tid >> 5, lane = tid & 31;
    const int q0 = blockIdx.x << 6;
    const int h  = blockIdx.y, b = blockIdx.z;
    const size_t hoff = (size_t)h * DKH;
    const int g = lane >> 2, t4 = lane & 3;

    const bf16* Qh_ = QKVh;          const bf16* Ql_ = QKVl;
    const bf16* Kh_ = QKVh + 1024;   const bf16* Kl_ = QKVl + 1024;
    const bf16* Vh_ = QKVh + 2048;   const bf16* Vl_ = QKVl + 2048;

    auto loadQ = [&](const bf16* __restrict__ src, uint32_t base) {
        #pragma unroll
        for (int i = 0; i < 4; i++) {
            const int ch = tid + (i << 7);
            const int r = ch >> 3, c = ch & 7;
            cpasync16(base + (uint32_t)r * AROWB + c * 16,
                      src + (size_t)(b * SEQ + q0 + r) * QKVLD + hoff + (c << 3));
        }
    };
    auto loadKV = [&](int blk, int slot) {
        const uint32_t base = sb + SM_KV + slot * ASTG;
        const bf16* srcs[4] = {Kh_, Kl_, Vh_, Vl_};
        #pragma unroll
        for (int tI = 0; tI < 4; tI++) {
            #pragma unroll
            for (int i = 0; i < 4; i++) {
                const int ch = tid + (i << 7);
                const int r = ch >> 3, c = ch & 7;
                cpasync16(base + tI * ATILE + (uint32_t)r * AROWB + c * 16,
                          srcs[tI] + (size_t)(b * SEQ + (blk << 6) + r) * QKVLD
                                   + hoff + (c << 3));
            }
        }
        if (tid < 16)
            cpasync16(sb + SM_MASK + slot * 256 + tid * 16,
                      mask + (size_t)b * SEQ + (blk << 6) + tid * 4);
    };

    loadQ(Qh_, sb);
    loadQ(Ql_, sb + ATILE);
    loadKV(0, 0);
    CP_COMMIT();

    uint32_t qh[4][4], ql[4][4];
    float o[8][4];
    #pragma unroll
    for (int i = 0; i < 8; i++)
        #pragma unroll
        for (int j = 0; j < 4; j++) o[i][j] = 0.f;
    float m0 = -INFINITY, m1 = -INFINITY, l0 = 0.f, l1 = 0.f;

    const uint32_t aoff = (uint32_t)((w * 16 + (lane & 15)) * AROWB)
                        + (((lane >> 4) & 1) << 4);
    const uint32_t boff = (uint32_t)((((lane >> 4) << 3) + (lane & 7)) * AROWB)
                        + (((lane >> 3) & 1) << 4);
    const uint32_t voff = (uint32_t)((lane & 15) * AROWB) + ((lane >> 4) << 4);

    const int NB = SEQ / 64;
    for (int it = 0; it < NB; ++it) {
        if (it + 1 < NB) { loadKV(it + 1, (it + 1) & 1); CP_COMMIT(); CP_WAIT1(); }
        else             { CP_WAIT0(); }
        __syncthreads();

        if (it == 0) {
            #pragma unroll
            for (int ks = 0; ks < 4; ks++) {
                ldm4(qh[ks], sb + aoff + ks * 32);
                ldm4(ql[ks], sb + ATILE + aoff + ks * 32);
            }
        }

        const uint32_t stg = sb + SM_KV + (it & 1) * ASTG;
        const int* msk = (const int*)(smem + SM_MASK + (it & 1) * 256);

        // ---- S = Q @ K^T (3-pass hi/lo) ----
        float sa[8][4];
        #pragma unroll
        for (int i = 0; i < 8; i++)
            #pragma unroll
            for (int j = 0; j < 4; j++) sa[i][j] = 0.f;

        #pragma unroll
        for (int ks = 0; ks < 4; ks++) {
            #pragma unroll
            for (int ng = 0; ng < 4; ng++) {
                uint32_t kh4[4], kl4[4];
                const uint32_t ad = stg + boff + ng * (16 * AROWB) + ks * 32;
                ldm4(kh4, ad);
                ldm4(kl4, ad + ATILE);
                float* c0 = sa[2*ng];
                float* c1 = sa[2*ng + 1];
                mma16816(c0, qh[ks], kh4[0], kh4[1]);
                mma16816(c1, qh[ks], kh4[2], kh4[3]);
                mma16816(c0, qh[ks], kl4[0], kl4[1]);
                mma16816(c1, qh[ks], kl4[2], kl4[3]);
                mma16816(c0, ql[ks], kh4[0], kh4[1]);
                mma16816(c1, ql[ks], kh4[2], kh4[3]);
            }
        }

        // ---- mask + scale ----
        #pragma unroll
        for (int nt = 0; nt < 8; nt++) {
            const int j0 = nt * 8 + (t4 << 1);
            const bool k0m = msk[j0] != 0, k1m = msk[j0 + 1] != 0;
            sa[nt][0] = k0m ? -1e9f : sa[nt][0] * 0.125f;
            sa[nt][1] = k1m ? -1e9f : sa[nt][1] * 0.125f;
            sa[nt][2] = k0m ? -1e9f : sa[nt][2] * 0.125f;
            sa[nt][3] = k1m ? -1e9f : sa[nt][3] * 0.125f;
        }

        // ---- online softmax ----
        float mx0 = -INFINITY, mx1 = -INFINITY;
        #pragma unroll
        for (int nt = 0; nt < 8; nt++) {
            mx0 = fmaxf(mx0, fmaxf(sa[nt][0], sa[nt][1]));
            mx1 = fmaxf(mx1, fmaxf(sa[nt][2], sa[nt][3]));
        }
        mx0 = fmaxf(mx0, __shfl_xor_sync(0xffffffffu, mx0, 1));
        mx0 = fmaxf(mx0, __shfl_xor_sync(0xffffffffu, mx0, 2));
        mx1 = fmaxf(mx1, __shfl_xor_sync(0xffffffffu, mx1, 1));
        mx1 = fmaxf(mx1, __shfl_xor_sync(0xffffffffu, mx1, 2));
        const float nm0 = fmaxf(m0, mx0), nm1 = fmaxf(m1, mx1);
        const float f0 = __expf(m0 - nm0), f1 = __expf(m1 - nm1);

        float s0 = 0.f, s1 = 0.f;
        #pragma unroll
        for (int nt = 0; nt < 8; nt++) {
            sa[nt][0] = __expf(sa[nt][0] - nm0);
            sa[nt][1] = __expf(sa[nt][1] - nm0);
            sa[nt][2] = __expf(sa[nt][2] - nm1);
            sa[nt][3] = __expf(sa[nt][3] - nm1);
            s0 += sa[nt][0] + sa[nt][1];
            s1 += sa[nt][2] + sa[nt][3];
        }
        s0 += __shfl_xor_sync(0xffffffffu, s0, 1);
        s0 += __shfl_xor_sync(0xffffffffu, s0, 2);
        s1 += __shfl_xor_sync(0xffffffffu, s1, 1);
        s1 += __shfl_xor_sync(0xffffffffu, s1, 2);
        m0 = nm0; m1 = nm1;
        l0 = l0 * f0 + s0;
        l1 = l1 * f1 + s1;
        #pragma unroll
        for (int d = 0; d < 8; d++) {
            o[d][0] *= f0; o[d][1] *= f0;
            o[d][2] *= f1; o[d][3] *= f1;
        }

        // ---- repack P, hi/lo split ----
        uint32_t pah[4][4], pal[4][4];
        #pragma unroll
        for (int ks = 0; ks < 4; ks++) {
            #pragma unroll
            for (int half = 0; half < 2; half++) {
                const float* sv = sa[2*ks + half];
                bf16 h0,lo0,h1,lo1,h2,lo2,h3,lo3;
                split_bf16(sv[0], h0, lo0); split_bf16(sv[1], h1, lo1);
                split_bf16(sv[2], h2, lo2); split_bf16(sv[3], h3, lo3);
                pah[ks][half*2 + 0] = packbf(h0, h1);
                pah[ks][half*2 + 1] = packbf(h2, h3);
                pal[ks][half*2 + 0] = packbf(lo0, lo1);
                pal[ks][half*2 + 1] = packbf(lo2, lo3);
            }
        }

        // ---- O += P @ V (3-pass hi/lo) ----
        #pragma unroll
        for (int ks = 0; ks < 4; ks++) {
            #pragma unroll
            for (int dg = 0; dg < 4; dg++) {
                uint32_t vh4[4], vl4[4];
                const uint32_t ad = stg + 2*ATILE + voff
                                  + ks * (16 * AROWB) + dg * 32;
                ldm4t(vh4, ad);
                ldm4t(vl4, ad + ATILE);
                float* c0 = o[2*dg];
                float* c1 = o[2*dg + 1];
                mma16816(c0, pah[ks], vh4[0], vh4[1]);
                mma16816(c1, pah[ks], vh4[2], vh4[3]);
                mma16816(c0, pah[ks], vl4[0], vl4[1]);
                mma16816(c1, pah[ks], vl4[2], vl4[3]);
                mma16816(c0, pal[ks], vh4[0], vh4[1]);
                mma16816(c1, pal[ks], vh4[2], vh4[3]);
            }
        }
        __syncthreads();
    }

    // ---- epilogue ----
    const float i0 = 1.f / l0, i1 = 1.f / l1;
    const size_t r0 = (size_t)(b * SEQ + q0 + w * 16 + g) * D_MODEL + hoff;
    const size_t r1 = r0 + (size_t)8 * D_MODEL;
    #pragma unroll
    for (int d = 0; d < 8; d++) {
        const int col = d * 8 + (t4 << 1);
        bf16 h0,lo0,h1,lo1;
        split_bf16(o[d][0] * i0, h0, lo0);
        split_bf16(o[d][1] * i0, h1, lo1);
        *(ushort2*)(Oh + r0 + col) = make_ushort2(__bfloat16_as_ushort(h0),
                                                  __bfloat16_as_ushort(h1));
        *(ushort2*)(Ol + r0 + col) = make_ushort2(__bfloat16_as_ushort(lo0),
                                                  __bfloat16_as_ushort(lo1));
        split_bf16(o[d][2] * i1, h0, lo0);
        split_bf16(o[d][3] * i1, h1, lo1);
        *(ushort2*)(Oh + r1 + col) = make_ushort2(__bfloat16_as_ushort(h0),
                                                  __bfloat16_as_ushort(h1));
        *(ushort2*)(Ol + r1 + col) = make_ushort2(__bfloat16_as_ushort(lo0),
                                                  __bfloat16_as_ushort(lo1));
    }
}

// ---------------- launch -----------------------------------------------------
extern "C" void kernel_launch(void* const* d_in, const int* in_sizes, int n_in,
                              void* d_out, int out_size)
{
    const float* x     = (const float*)d_in[0];
    const float* w_q   = (const float*)d_in[1];
    const float* w_k   = (const float*)d_in[2];
    const float* w_v   = (const float*)d_in[3];
    const float* w_o   = (const float*)d_in[4];
    const float* l1_w  = (const float*)d_in[5];
    const float* l1_b  = (const float*)d_in[6];
    const float* l2_w  = (const float*)d_in[7];
    const float* l2_b  = (const float*)d_in[8];
    const float* n1a   = (const float*)d_in[9];
    const float* n1b   = (const float*)d_in[10];
    const float* n2a   = (const float*)d_in[11];
    const float* n2b   = (const float*)d_in[12];
    const float* nfa   = (const float*)d_in[13];
    const float* nfb   = (const float*)d_in[14];
    const int*   mask  = (const int*)d_in[15];
    float* out = (float*)d_out;

    float *x1, *x2;
    bf16 *xnh,*xnl,*qkvh,*qkvl,*hh,*hl,*aoh,*aol,*ffh,*ffl;
    bf16 *wqkvh,*wqkvl,*woh,*wol,*l1h,*l1l,*l2h,*l2l;
    cudaGetSymbolAddress((void**)&x1, g_x1);
    cudaGetSymbolAddress((void**)&x2, g_x2);
    cudaGetSymbolAddress((void**)&xnh, g_xnh); cudaGetSymbolAddress((void**)&xnl, g_xnl);
    cudaGetSymbolAddress((void**)&qkvh, g_qkvh); cudaGetSymbolAddress((void**)&qkvl, g_qkvl);
    cudaGetSymbolAddress((void**)&hh,  g_hh);  cudaGetSymbolAddress((void**)&hl,  g_hl);
    cudaGetSymbolAddress((void**)&aoh, g_aoh); cudaGetSymbolAddress((void**)&aol, g_aol);
    cudaGetSymbolAddress((void**)&ffh, g_ffh); cudaGetSymbolAddress((void**)&ffl, g_ffl);
    cudaGetSymbolAddress((void**)&wqkvh, g_wqkvh); cudaGetSymbolAddress((void**)&wqkvl, g_wqkvl);
    cudaGetSymbolAddress((void**)&woh, g_woh); cudaGetSymbolAddress((void**)&wol, g_wol);
    cudaGetSymbolAddress((void**)&l1h, g_l1h); cudaGetSymbolAddress((void**)&l1l, g_l1l);
    cudaGetSymbolAddress((void**)&l2h, g_l2h); cudaGetSymbolAddress((void**)&l2l, g_l2l);

    cudaFuncSetAttribute(gemm_tc<false,false,false,true>,
        cudaFuncAttributeMaxDynamicSharedMemorySize, GEMM_SMEM);
    cudaFuncSetAttribute(gemm_tc<false,false,true,false>,
        cudaFuncAttributeMaxDynamicSharedMemorySize, GEMM_SMEM);
    cudaFuncSetAttribute(gemm_tc<true,true,false,true>,
        cudaFuncAttributeMaxDynamicSharedMemorySize, GEMM_SMEM);
    cudaFuncSetAttribute(gemm_tc<false,true,true,false>,
        cudaFuncAttributeMaxDynamicSharedMemorySize, GEMM_SMEM);
    cudaFuncSetAttribute(attn_tc,
        cudaFuncAttributeMaxDynamicSharedMemorySize, ATTN_SMEM);

    const int nDD4 = D_MODEL*D_MODEL/4, nFD4 = D_FF*D_MODEL/4;
    // fused QKV weights: rows 0..1023 = w_q, 1024..2047 = w_k, 2048..3071 = w_v
    cvt_kernel<<<(nDD4+255)/256, 256>>>((const float4*)w_q,
        (ushort4*)wqkvh,                     (ushort4*)wqkvl,                     nDD4);
    cvt_kernel<<<(nDD4+255)/256, 256>>>((const float4*)w_k,
        (ushort4*)(wqkvh + 1024*1024),       (ushort4*)(wqkvl + 1024*1024),       nDD4);
    cvt_kernel<<<(nDD4+255)/256, 256>>>((const float4*)w_v,
        (ushort4*)(wqkvh + 2048*1024),       (ushort4*)(wqkvl + 2048*1024),       nDD4);
    cvt_kernel<<<(nDD4+255)/256, 256>>>((const float4*)w_o,  (ushort4*)woh, (ushort4*)wol, nDD4);
    cvt_kernel<<<(nFD4+255)/256, 256>>>((const float4*)l1_w, (ushort4*)l1h, (ushort4*)l1l, nFD4);
    cvt_kernel<<<(nFD4+255)/256, 256>>>((const float4*)l2_w, (ushort4*)l2h, (ushort4*)l2l, nFD4);

    const dim3 gQKV(QKVN/128,   NROWS/128);
    const dim3 gD  (D_MODEL/128, NROWS/128);
    const dim3 gF  (D_FF/128,    NROWS/128);

    // 1) xn = LN1(x) -> bf16 hi/lo
    ln_kernel<true><<<NROWS, 256>>>(x, n1a, n1b, nullptr, xnh, xnl);
    // 2) fused QKV GEMM -> bf16 hi/lo [rows, 3072]
    gemm_tc<false,false,false,true><<<gQKV, 256, GEMM_SMEM>>>(
        xnh, xnl, wqkvh, wqkvl, nullptr, nullptr, nullptr, qkvh, qkvl,
        NROWS, QKVN, D_MODEL);
    // 3) attention (tensor cores) -> bf16 hi/lo
    attn_tc<<<dim3(SEQ/64, NH, BATCH), 128, ATTN_SMEM>>>(
        qkvh, qkvl, mask, aoh, aol);
    // 4) x1 = x + ao @ w_o^T (fp32)
    gemm_tc<false,false,true,false><<<gD, 256, GEMM_SMEM>>>(
        aoh, aol, woh, wol, nullptr, x, x1, nullptr, nullptr, NROWS, D_MODEL, D_MODEL);
    // 5) h = LN2(x1) -> bf16 hi/lo
    ln_kernel<true><<<NROWS, 256>>>(x1, n2a, n2b, nullptr, hh, hl);
    // 6) ff = relu(h @ l1^T + b1) -> bf16 hi/lo
    gemm_tc<true,true,false,true><<<gF, 256, GEMM_SMEM>>>(
        hh, hl, l1h, l1l, l1_b, nullptr, nullptr, ffh, ffl, NROWS, D_FF, D_MODEL);
    // 7) x2 = x1 + ff @ l2^T + b2 (fp32)
    gemm_tc<false,true,true,false><<<gD, 256, GEMM_SMEM>>>(
        ffh, ffl, l2h, l2l, l2_b, x1, x2, nullptr, nullptr, NROWS, D_MODEL, D_FF);
    // 8) out = LNf(x2)
    ln_kernel<false><<<NROWS, 256>>>(x2, nfa, nfb, out, nullptr, nullptr);
}

// round 7
// speedup vs baseline: 5.0003x; 1.4582x over previous
#include <cuda_runtime.h>
#include <cuda_fp16.h>
#include <math.h>
#include <stdint.h>

#define D_MODEL 1024
#define NH      16
#define DKH     64
#define D_FF    4096
#define BATCH   4
#define SEQ     2048
#define NROWS   (BATCH*SEQ)
#define QKVN    3072
#define QKVLD   3072

typedef __half f16;

// ---------------- scratch (device globals; no runtime allocation) ----------
__device__ float g_x1[NROWS * D_MODEL];
__device__ float g_x2[NROWS * D_MODEL];

__device__ f16 g_xnh[NROWS * D_MODEL];
__device__ f16 g_qkvh[(size_t)NROWS * QKVN], g_qkvl[(size_t)NROWS * QKVN];
__device__ f16 g_hh [NROWS * D_MODEL];
__device__ f16 g_aoh[NROWS * D_MODEL];
__device__ f16 g_ffh[(size_t)NROWS * D_FF];

__device__ f16 g_wqkvh[QKVN*D_MODEL], g_wqkvl[QKVN*D_MODEL];
__device__ f16 g_woh[D_MODEL*D_MODEL], g_wol[D_MODEL*D_MODEL];
__device__ f16 g_l1h[D_FF*D_MODEL],   g_l1l[D_FF*D_MODEL];
__device__ f16 g_l2h[D_MODEL*D_FF],   g_l2l[D_MODEL*D_FF];

// ---------------- small PTX helpers ----------------------------------------
__device__ __forceinline__ uint32_t smem_u32(const void* p) {
    uint32_t a;
    asm("{ .reg .u64 t; cvta.to.shared.u64 t, %1; cvt.u32.u64 %0, t; }"
        : "=r"(a) : "l"(p));
    return a;
}
__device__ __forceinline__ void cpasync16(uint32_t dst, const void* src) {
    asm volatile("cp.async.cg.shared.global [%0], [%1], 16;"
                 :: "r"(dst), "l"(src));
}
#define CP_COMMIT() asm volatile("cp.async.commit_group;" ::: "memory")
#define CP_WAIT1()  asm volatile("cp.async.wait_group 1;" ::: "memory")
#define CP_WAIT0()  asm volatile("cp.async.wait_group 0;" ::: "memory")

__device__ __forceinline__ void ldm4(uint32_t* r, uint32_t addr) {
    asm volatile("ldmatrix.sync.aligned.m8n8.x4.shared.b16 {%0,%1,%2,%3}, [%4];"
        : "=r"(r[0]), "=r"(r[1]), "=r"(r[2]), "=r"(r[3]) : "r"(addr));
}
__device__ __forceinline__ void ldm4t(uint32_t* r, uint32_t addr) {
    asm volatile("ldmatrix.sync.aligned.m8n8.x4.trans.shared.b16 {%0,%1,%2,%3}, [%4];"
        : "=r"(r[0]), "=r"(r[1]), "=r"(r[2]), "=r"(r[3]) : "r"(addr));
}
__device__ __forceinline__ void mma16816(float* c, const uint32_t* a,
                                         uint32_t b0, uint32_t b1) {
    asm volatile("mma.sync.aligned.m16n8k16.row.col.f32.f16.f16.f32 "
        "{%0,%1,%2,%3}, {%4,%5,%6,%7}, {%8,%9}, {%0,%1,%2,%3};"
        : "+f"(c[0]), "+f"(c[1]), "+f"(c[2]), "+f"(c[3])
        : "r"(a[0]), "r"(a[1]), "r"(a[2]), "r"(a[3]), "r"(b0), "r"(b1));
}

__device__ __forceinline__ void split_f16(float f, f16& h, f16& l) {
    h = __float2half_rn(f);
    l = __float2half_rn(f - __half2float(h));
}
__device__ __forceinline__ uint32_t packh(f16 a, f16 b) {
    return (uint32_t)__half_as_ushort(a) |
           ((uint32_t)__half_as_ushort(b) << 16);
}

// ---------------- weight fp32 -> fp16 hi/lo conversion ----------------------
__global__ __launch_bounds__(256) void cvt_kernel(
    const float4* __restrict__ src, ushort4* __restrict__ hi,
    ushort4* __restrict__ lo, int n4)
{
    int i = blockIdx.x * 256 + threadIdx.x;
    if (i >= n4) return;
    float4 v = src[i];
    f16 h0,l0,h1,l1,h2,l2,h3,l3;
    split_f16(v.x, h0, l0); split_f16(v.y, h1, l1);
    split_f16(v.z, h2, l2); split_f16(v.w, h3, l3);
    hi[i] = make_ushort4(__half_as_ushort(h0), __half_as_ushort(h1),
                         __half_as_ushort(h2), __half_as_ushort(h3));
    lo[i] = make_ushort4(__half_as_ushort(l0), __half_as_ushort(l1),
                         __half_as_ushort(l2), __half_as_ushort(l3));
}

// ---------------- layernorm (unbiased std) ----------------------------------
__device__ __forceinline__ float block_sum(float v, float* red) {
    __syncthreads();
    #pragma unroll
    for (int o = 16; o; o >>= 1) v += __shfl_xor_sync(0xffffffffu, v, o);
    int tid = threadIdx.x;
    if ((tid & 31) == 0) red[tid >> 5] = v;
    __syncthreads();
    if (tid == 0) {
        float t = 0.f;
        #pragma unroll
        for (int i = 0; i < 8; i++) t += red[i];
        red[0] = t;
    }
    __syncthreads();
    return red[0];
}

template<bool F16OUT>
__global__ __launch_bounds__(256) void ln_kernel(
    const float* __restrict__ x, const float* __restrict__ ga,
    const float* __restrict__ gb, float* __restrict__ out,
    f16* __restrict__ oh)
{
    __shared__ float red[8];
    const int row = blockIdx.x;
    const int tid = threadIdx.x;
    const float4 v = reinterpret_cast<const float4*>(x + (size_t)row * D_MODEL)[tid];

    float s = v.x + v.y + v.z + v.w;
    const float mean = block_sum(s, red) * (1.0f / D_MODEL);

    float4 d = make_float4(v.x - mean, v.y - mean, v.z - mean, v.w - mean);
    float sq = d.x*d.x + d.y*d.y + d.z*d.z + d.w*d.w;
    const float var = block_sum(sq, red) * (1.0f / (D_MODEL - 1));
    const float rstd = rsqrtf(var);

    const float4 a = reinterpret_cast<const float4*>(ga)[tid];
    const float4 b = reinterpret_cast<const float4*>(gb)[tid];
    float4 o;
    o.x = d.x * rstd * a.x + b.x;
    o.y = d.y * rstd * a.y + b.y;
    o.z = d.z * rstd * a.z + b.z;
    o.w = d.w * rstd * a.w + b.w;
    if (F16OUT) {
        const size_t idx = (size_t)row * (D_MODEL/4) + tid;
        reinterpret_cast<ushort4*>(oh)[idx] = make_ushort4(
            __half_as_ushort(__float2half_rn(o.x)),
            __half_as_ushort(__float2half_rn(o.y)),
            __half_as_ushort(__float2half_rn(o.z)),
            __half_as_ushort(__float2half_rn(o.w)));
    } else {
        reinterpret_cast<float4*>(out + (size_t)row * D_MODEL)[tid] = o;
    }
}

// ---------------- mma.sync fp16 2-pass GEMM ----------------------------------
// C = A(fp16) @ [Wh + Wl](fp16)^T, fp32 accum. BM=BN=128, BK=32,
// 3-stage cp.async pipeline (loads issued 2 iters ahead), 2 CTAs/SM.
// OMODE: 0 = fp32 out, 1 = fp16 single out, 2 = fp16 hi/lo out.
#define NSTG      3
#define ROWB      80
#define TILE_B    (128*ROWB)
#define STAGE_B   (3*TILE_B)          // Ah, Wh, Wl
#define GEMM_SMEM (NSTG*STAGE_B)      // 92160 B

template<bool RELU, bool HASB, bool HASR, int OMODE>
__global__ __launch_bounds__(256, 2) void gemm_tc(
    const f16* __restrict__ Ah,
    const f16* __restrict__ Wh, const f16* __restrict__ Wl,
    const float* __restrict__ bias, const float* __restrict__ res,
    float* __restrict__ C, f16* __restrict__ Ch, f16* __restrict__ Cl,
    int M, int N, int K)
{
    extern __shared__ char smem[];
    const uint32_t sb = smem_u32(smem);
    const int tid  = threadIdx.x;
    const int bm   = blockIdx.y << 7;
    const int bn   = blockIdx.x << 7;
    const int w    = tid >> 5, lane = tid & 31;
    const int mblock = (w & 3) << 5;
    const int nblock = (w >> 2) << 6;

    const uint32_t aRowByte = (uint32_t)(mblock + (lane & 15)) * ROWB
                            + ((lane >> 4) & 1) * 16;
    const uint32_t bRowByte = (uint32_t)(nblock + ((lane >> 4) << 3) + (lane & 7)) * ROWB
                            + ((lane >> 3) & 1) * 16;

    float acc[2][8][4];
    #pragma unroll
    for (int i = 0; i < 2; i++)
        #pragma unroll
        for (int j = 0; j < 8; j++)
            #pragma unroll
            for (int t = 0; t < 4; t++) acc[i][j][t] = 0.f;

    auto load1 = [&](const f16* __restrict__ src, int row0, uint32_t sbase, int kt) {
        #pragma unroll
        for (int i = 0; i < 2; i++) {
            const int ch = tid + (i << 8);
            const int r = ch >> 2, c = ch & 3;
            cpasync16(sbase + (uint32_t)r * ROWB + c * 16,
                      src + (size_t)(row0 + r) * K + (kt << 5) + (c << 3));
        }
    };
    auto load_stage = [&](int kt, int slot) {
        const uint32_t base = sb + slot * STAGE_B;
        load1(Ah, bm, base,            kt);
        load1(Wh, bn, base + TILE_B,   kt);
        load1(Wl, bn, base + 2*TILE_B, kt);
    };

    const int NK = K >> 5;
    load_stage(0, 0); CP_COMMIT();
    load_stage(1, 1); CP_COMMIT();

    int slot = 0;
    for (int kt = 0; kt < NK; ++kt) {
        CP_WAIT1();
        __syncthreads();

        const int nt = kt + 2;
        if (nt < NK) load_stage(nt, nt % NSTG);
        CP_COMMIT();

        const uint32_t st = sb + slot * STAGE_B;
        slot = (slot + 1 == NSTG) ? 0 : slot + 1;
        const uint32_t aHi = st + aRowByte;
        const uint32_t bHi = st + TILE_B + bRowByte;
        const uint32_t bLo = bHi + TILE_B;

        #pragma unroll
        for (int ks = 0; ks < 2; ++ks) {
            uint32_t ah[2][4];
            #pragma unroll
            for (int mt = 0; mt < 2; mt++)
                ldm4(ah[mt], aHi + mt*(16*ROWB) + ks*32);
            #pragma unroll
            for (int np = 0; np < 4; np++) {
                uint32_t bh4[4], bl4[4];
                ldm4(bh4, bHi + np*(16*ROWB) + ks*32);
                ldm4(bl4, bLo + np*(16*ROWB) + ks*32);
                #pragma unroll
                for (int mt = 0; mt < 2; mt++)
                    #pragma unroll
                    for (int h = 0; h < 2; h++) {
                        float* c = acc[mt][np*2 + h];
                        mma16816(c, ah[mt], bh4[h*2], bh4[h*2+1]);
                        mma16816(c, ah[mt], bl4[h*2], bl4[h*2+1]);
                    }
            }
        }
    }

    #pragma unroll
    for (int mt = 0; mt < 2; mt++) {
        #pragma unroll
        for (int nt = 0; nt < 8; nt++) {
            const int r0 = bm + mblock + mt*16 + (lane >> 2);
            const int c0 = bn + nblock + nt*8 + ((lane & 3) << 1);
            float v00 = acc[mt][nt][0], v01 = acc[mt][nt][1];
            float v10 = acc[mt][nt][2], v11 = acc[mt][nt][3];
            if (HASB) {
                const float2 bb = *(const float2*)(bias + c0);
                v00 += bb.x; v01 += bb.y; v10 += bb.x; v11 += bb.y;
            }
            if (RELU) {
                v00 = fmaxf(v00, 0.f); v01 = fmaxf(v01, 0.f);
                v10 = fmaxf(v10, 0.f); v11 = fmaxf(v11, 0.f);
            }
            const size_t o0 = (size_t)r0 * N + c0;
            const size_t o1 = o0 + (size_t)8 * N;
            if (HASR) {
                const float2 r4a = *(const float2*)(res + o0);
                const float2 r4b = *(const float2*)(res + o1);
                v00 += r4a.x; v01 += r4a.y; v10 += r4b.x; v11 += r4b.y;
            }
            if (OMODE == 0) {
                *(float2*)(C + o0) = make_float2(v00, v01);
                *(float2*)(C + o1) = make_float2(v10, v11);
            } else if (OMODE == 1) {
                *(uint32_t*)(Ch + o0) = packh(__float2half_rn(v00), __float2half_rn(v01));
                *(uint32_t*)(Ch + o1) = packh(__float2half_rn(v10), __float2half_rn(v11));
            } else {
                f16 h0,l0,h1,l1;
                split_f16(v00, h0, l0); split_f16(v01, h1, l1);
                *(uint32_t*)(Ch + o0) = packh(h0, h1);
                *(uint32_t*)(Cl + o0) = packh(l0, l1);
                split_f16(v10, h0, l0); split_f16(v11, h1, l1);
                *(uint32_t*)(Ch + o1) = packh(h0, h1);
                *(uint32_t*)(Cl + o1) = packh(l0, l1);
            }
        }
    }
}

// ---------------- tensor-core flash attention (fp16 2-pass) ------------------
// Q single fp16; K/V hi+lo fp16 (B-side of their MMAs). P single fp16.
#define AROWB 144
#define ATILE (64*AROWB)              // 9216 B
#define ASTG  (4*ATILE)               // Kh, Kl, Vh, Vl
#define SM_KV ATILE                   // after Qh
#define SM_MASK (SM_KV + 2*ASTG)
#define ATTN_SMEM (SM_MASK + 512)     // 83456 B

__global__ __launch_bounds__(128) void attn_tc(
    const f16* __restrict__ QKVh, const f16* __restrict__ QKVl,
    const int* __restrict__ mask,
    f16* __restrict__ Oh)
{
    extern __shared__ char smem[];
    const uint32_t sb = smem_u32(smem);
    const int tid = threadIdx.x, w = tid >> 5, lane = tid & 31;
    const int q0 = blockIdx.x << 6;
    const int h  = blockIdx.y, b = blockIdx.z;
    const size_t hoff = (size_t)h * DKH;
    const int g = lane >> 2, t4 = lane & 3;

    const f16* Qh_ = QKVh;
    const f16* Kh_ = QKVh + 1024;   const f16* Kl_ = QKVl + 1024;
    const f16* Vh_ = QKVh + 2048;   const f16* Vl_ = QKVl + 2048;

    // Q tile (64 x 64 fp16)
    #pragma unroll
    for (int i = 0; i < 4; i++) {
        const int ch = tid + (i << 7);
        const int r = ch >> 3, c = ch & 7;
        cpasync16(sb + (uint32_t)r * AROWB + c * 16,
                  Qh_ + (size_t)(b * SEQ + q0 + r) * QKVLD + hoff + (c << 3));
    }
    auto loadKV = [&](int blk, int slot) {
        const uint32_t base = sb + SM_KV + slot * ASTG;
        const f16* srcs[4] = {Kh_, Kl_, Vh_, Vl_};
        #pragma unroll
        for (int tI = 0; tI < 4; tI++) {
            #pragma unroll
            for (int i = 0; i < 4; i++) {
                const int ch = tid + (i << 7);
                const int r = ch >> 3, c = ch & 7;
                cpasync16(base + tI * ATILE + (uint32_t)r * AROWB + c * 16,
                          srcs[tI] + (size_t)(b * SEQ + (blk << 6) + r) * QKVLD
                                   + hoff + (c << 3));
            }
        }
        if (tid < 16)
            cpasync16(sb + SM_MASK + slot * 256 + tid * 16,
                      mask + (size_t)b * SEQ + (blk << 6) + tid * 4);
    };

    loadKV(0, 0);
    CP_COMMIT();

    uint32_t qh[4][4];
    float o[8][4];
    #pragma unroll
    for (int i = 0; i < 8; i++)
        #pragma unroll
        for (int j = 0; j < 4; j++) o[i][j] = 0.f;
    float m0 = -INFINITY, m1 = -INFINITY, l0 = 0.f, l1 = 0.f;

    const uint32_t aoff = (uint32_t)((w * 16 + (lane & 15)) * AROWB)
                        + (((lane >> 4) & 1) << 4);
    const uint32_t boff = (uint32_t)((((lane >> 4) << 3) + (lane & 7)) * AROWB)
                        + (((lane >> 3) & 1) << 4);
    const uint32_t voff = (uint32_t)((lane & 15) * AROWB) + ((lane >> 4) << 4);

    const int NB = SEQ / 64;
    for (int it = 0; it < NB; ++it) {
        if (it + 1 < NB) { loadKV(it + 1, (it + 1) & 1); CP_COMMIT(); CP_WAIT1(); }
        else             { CP_WAIT0(); }
        __syncthreads();

        if (it == 0) {
            #pragma unroll
            for (int ks = 0; ks < 4; ks++)
                ldm4(qh[ks], sb + aoff + ks * 32);
        }

        const uint32_t stg = sb + SM_KV + (it & 1) * ASTG;
        const int* msk = (const int*)(smem + SM_MASK + (it & 1) * 256);

        // ---- S = Q @ (Kh + Kl)^T (2-pass) ----
        float sa[8][4];
        #pragma unroll
        for (int i = 0; i < 8; i++)
            #pragma unroll
            for (int j = 0; j < 4; j++) sa[i][j] = 0.f;

        #pragma unroll
        for (int ks = 0; ks < 4; ks++) {
            #pragma unroll
            for (int ng = 0; ng < 4; ng++) {
                uint32_t kh4[4], kl4[4];
                const uint32_t ad = stg + boff + ng * (16 * AROWB) + ks * 32;
                ldm4(kh4, ad);
                ldm4(kl4, ad + ATILE);
                float* c0 = sa[2*ng];
                float* c1 = sa[2*ng + 1];
                mma16816(c0, qh[ks], kh4[0], kh4[1]);
                mma16816(c1, qh[ks], kh4[2], kh4[3]);
                mma16816(c0, qh[ks], kl4[0], kl4[1]);
                mma16816(c1, qh[ks], kl4[2], kl4[3]);
            }
        }

        // ---- mask + scale ----
        #pragma unroll
        for (int nt = 0; nt < 8; nt++) {
            const int j0 = nt * 8 + (t4 << 1);
            const bool k0m = msk[j0] != 0, k1m = msk[j0 + 1] != 0;
            sa[nt][0] = k0m ? -1e9f : sa[nt][0] * 0.125f;
            sa[nt][1] = k1m ? -1e9f : sa[nt][1] * 0.125f;
            sa[nt][2] = k0m ? -1e9f : sa[nt][2] * 0.125f;
            sa[nt][3] = k1m ? -1e9f : sa[nt][3] * 0.125f;
        }

        // ---- online softmax ----
        float mx0 = -INFINITY, mx1 = -INFINITY;
        #pragma unroll
        for (int nt = 0; nt < 8; nt++) {
            mx0 = fmaxf(mx0, fmaxf(sa[nt][0], sa[nt][1]));
            mx1 = fmaxf(mx1, fmaxf(sa[nt][2], sa[nt][3]));
        }
        mx0 = fmaxf(mx0, __shfl_xor_sync(0xffffffffu, mx0, 1));
        mx0 = fmaxf(mx0, __shfl_xor_sync(0xffffffffu, mx0, 2));
        mx1 = fmaxf(mx1, __shfl_xor_sync(0xffffffffu, mx1, 1));
        mx1 = fmaxf(mx1, __shfl_xor_sync(0xffffffffu, mx1, 2));
        const float nm0 = fmaxf(m0, mx0), nm1 = fmaxf(m1, mx1);
        const float f0 = __expf(m0 - nm0), f1 = __expf(m1 - nm1);

        float s0 = 0.f, s1 = 0.f;
        #pragma unroll
        for (int nt = 0; nt < 8; nt++) {
            sa[nt][0] = __expf(sa[nt][0] - nm0);
            sa[nt][1] = __expf(sa[nt][1] - nm0);
            sa[nt][2] = __expf(sa[nt][2] - nm1);
            sa[nt][3] = __expf(sa[nt][3] - nm1);
            s0 += sa[nt][0] + sa[nt][1];
            s1 += sa[nt][2] + sa[nt][3];
        }
        s0 += __shfl_xor_sync(0xffffffffu, s0, 1);
        s0 += __shfl_xor_sync(0xffffffffu, s0, 2);
        s1 += __shfl_xor_sync(0xffffffffu, s1, 1);
        s1 += __shfl_xor_sync(0xffffffffu, s1, 2);
        m0 = nm0; m1 = nm1;
        l0 = l0 * f0 + s0;
        l1 = l1 * f1 + s1;
        #pragma unroll
        for (int d = 0; d < 8; d++) {
            o[d][0] *= f0; o[d][1] *= f0;
            o[d][2] *= f1; o[d][3] *= f1;
        }

        // ---- repack P (single fp16 a-fragments) ----
        uint32_t pah[4][4];
        #pragma unroll
        for (int ks = 0; ks < 4; ks++) {
            #pragma unroll
            for (int half = 0; half < 2; half++) {
                const float* sv = sa[2*ks + half];
                pah[ks][half*2 + 0] = packh(__float2half_rn(sv[0]),
                                            __float2half_rn(sv[1]));
                pah[ks][half*2 + 1] = packh(__float2half_rn(sv[2]),
                                            __float2half_rn(sv[3]));
            }
        }

        // ---- O += P @ (Vh + Vl) (2-pass) ----
        #pragma unroll
        for (int ks = 0; ks < 4; ks++) {
            #pragma unroll
            for (int dg = 0; dg < 4; dg++) {
                uint32_t vh4[4], vl4[4];
                const uint32_t ad = stg + 2*ATILE + voff
                                  + ks * (16 * AROWB) + dg * 32;
                ldm4t(vh4, ad);
                ldm4t(vl4, ad + ATILE);
                float* c0 = o[2*dg];
                float* c1 = o[2*dg + 1];
                mma16816(c0, pah[ks], vh4[0], vh4[1]);
                mma16816(c1, pah[ks], vh4[2], vh4[3]);
                mma16816(c0, pah[ks], vl4[0], vl4[1]);
                mma16816(c1, pah[ks], vl4[2], vl4[3]);
            }
        }
        __syncthreads();
    }

    // ---- epilogue: normalize, store single fp16 ----
    const float i0 = 1.f / l0, i1 = 1.f / l1;
    const size_t r0 = (size_t)(b * SEQ + q0 + w * 16 + g) * D_MODEL + hoff;
    const size_t r1 = r0 + (size_t)8 * D_MODEL;
    #pragma unroll
    for (int d = 0; d < 8; d++) {
        const int col = d * 8 + (t4 << 1);
        *(uint32_t*)(Oh + r0 + col) = packh(__float2half_rn(o[d][0] * i0),
                                            __float2half_rn(o[d][1] * i0));
        *(uint32_t*)(Oh + r1 + col) = packh(__float2half_rn(o[d][2] * i1),
                                            __float2half_rn(o[d][3] * i1));
    }
}

// ---------------- launch -----------------------------------------------------
extern "C" void kernel_launch(void* const* d_in, const int* in_sizes, int n_in,
                              void* d_out, int out_size)
{
    const float* x     = (const float*)d_in[0];
    const float* w_q   = (const float*)d_in[1];
    const float* w_k   = (const float*)d_in[2];
    const float* w_v   = (const float*)d_in[3];
    const float* w_o   = (const float*)d_in[4];
    const float* l1_w  = (const float*)d_in[5];
    const float* l1_b  = (const float*)d_in[6];
    const float* l2_w  = (const float*)d_in[7];
    const float* l2_b  = (const float*)d_in[8];
    const float* n1a   = (const float*)d_in[9];
    const float* n1b   = (const float*)d_in[10];
    const float* n2a   = (const float*)d_in[11];
    const float* n2b   = (const float*)d_in[12];
    const float* nfa   = (const float*)d_in[13];
    const float* nfb   = (const float*)d_in[14];
    const int*   mask  = (const int*)d_in[15];
    float* out = (float*)d_out;

    float *x1, *x2;
    f16 *xnh,*qkvh,*qkvl,*hh,*aoh,*ffh;
    f16 *wqkvh,*wqkvl,*woh,*wol,*l1h,*l1l,*l2h,*l2l;
    cudaGetSymbolAddress((void**)&x1, g_x1);
    cudaGetSymbolAddress((void**)&x2, g_x2);
    cudaGetSymbolAddress((void**)&xnh, g_xnh);
    cudaGetSymbolAddress((void**)&qkvh, g_qkvh); cudaGetSymbolAddress((void**)&qkvl, g_qkvl);
    cudaGetSymbolAddress((void**)&hh,  g_hh);
    cudaGetSymbolAddress((void**)&aoh, g_aoh);
    cudaGetSymbolAddress((void**)&ffh, g_ffh);
    cudaGetSymbolAddress((void**)&wqkvh, g_wqkvh); cudaGetSymbolAddress((void**)&wqkvl, g_wqkvl);
    cudaGetSymbolAddress((void**)&woh, g_woh); cudaGetSymbolAddress((void**)&wol, g_wol);
    cudaGetSymbolAddress((void**)&l1h, g_l1h); cudaGetSymbolAddress((void**)&l1l, g_l1l);
    cudaGetSymbolAddress((void**)&l2h, g_l2h); cudaGetSymbolAddress((void**)&l2l, g_l2l);

    cudaFuncSetAttribute(gemm_tc<false,false,false,2>,
        cudaFuncAttributeMaxDynamicSharedMemorySize, GEMM_SMEM);
    cudaFuncSetAttribute(gemm_tc<false,false,true,0>,
        cudaFuncAttributeMaxDynamicSharedMemorySize, GEMM_SMEM);
    cudaFuncSetAttribute(gemm_tc<true,true,false,1>,
        cudaFuncAttributeMaxDynamicSharedMemorySize, GEMM_SMEM);
    cudaFuncSetAttribute(gemm_tc<false,true,true,0>,
        cudaFuncAttributeMaxDynamicSharedMemorySize, GEMM_SMEM);
    cudaFuncSetAttribute(attn_tc,
        cudaFuncAttributeMaxDynamicSharedMemorySize, ATTN_SMEM);

    const int nDD4 = D_MODEL*D_MODEL/4, nFD4 = D_FF*D_MODEL/4;
    // fused QKV weights: rows 0..1023 = w_q, 1024..2047 = w_k, 2048..3071 = w_v
    cvt_kernel<<<(nDD4+255)/256, 256>>>((const float4*)w_q,
        (ushort4*)wqkvh,               (ushort4*)wqkvl,               nDD4);
    cvt_kernel<<<(nDD4+255)/256, 256>>>((const float4*)w_k,
        (ushort4*)(wqkvh + 1024*1024), (ushort4*)(wqkvl + 1024*1024), nDD4);
    cvt_kernel<<<(nDD4+255)/256, 256>>>((const float4*)w_v,
        (ushort4*)(wqkvh + 2048*1024), (ushort4*)(wqkvl + 2048*1024), nDD4);
    cvt_kernel<<<(nDD4+255)/256, 256>>>((const float4*)w_o,  (ushort4*)woh, (ushort4*)wol, nDD4);
    cvt_kernel<<<(nFD4+255)/256, 256>>>((const float4*)l1_w, (ushort4*)l1h, (ushort4*)l1l, nFD4);
    cvt_kernel<<<(nFD4+255)/256, 256>>>((const float4*)l2_w, (ushort4*)l2h, (ushort4*)l2l, nFD4);

    const dim3 gQKV(QKVN/128,   NROWS/128);
    const dim3 gD  (D_MODEL/128, NROWS/128);
    const dim3 gF  (D_FF/128,    NROWS/128);

    // 1) xn = LN1(x) -> fp16
    ln_kernel<true><<<NROWS, 256>>>(x, n1a, n1b, nullptr, xnh);
    // 2) fused QKV GEMM -> fp16 hi/lo [rows, 3072]
    gemm_tc<false,false,false,2><<<gQKV, 256, GEMM_SMEM>>>(
        xnh, wqkvh, wqkvl, nullptr, nullptr, nullptr, qkvh, qkvl,
        NROWS, QKVN, D_MODEL);
    // 3) attention -> fp16
    attn_tc<<<dim3(SEQ/64, NH, BATCH), 128, ATTN_SMEM>>>(qkvh, qkvl, mask, aoh);
    // 4) x1 = x + ao @ w_o^T (fp32)
    gemm_tc<false,false,true,0><<<gD, 256, GEMM_SMEM>>>(
        aoh, woh, wol, nullptr, x, x1, nullptr, nullptr, NROWS, D_MODEL, D_MODEL);
    // 5) h = LN2(x1) -> fp16
    ln_kernel<true><<<NROWS, 256>>>(x1, n2a, n2b, nullptr, hh);
    // 6) ff = relu(h @ l1^T + b1) -> fp16
    gemm_tc<true,true,false,1><<<gF, 256, GEMM_SMEM>>>(
        hh, l1h, l1l, l1_b, nullptr, nullptr, ffh, nullptr, NROWS, D_FF, D_MODEL);
    // 7) x2 = x1 + ff @ l2^T + b2 (fp32)
    gemm_tc<false,true,true,0><<<gD, 256, GEMM_SMEM>>>(
        ffh, l2h, l2l, l2_b, x1, x2, nullptr, nullptr, NROWS, D_MODEL, D_FF);
    // 8) out = LNf(x2)
    ln_kernel<false><<<NROWS, 256>>>(x2, nfa, nfb, out, nullptr);
}

// round 8
// speedup vs baseline: 8.6112x; 1.7222x over previous
#include <cuda_runtime.h>
#include <cuda_fp16.h>
#include <math.h>
#include <stdint.h>

#define D_MODEL 1024
#define NH      16
#define DKH     64
#define D_FF    4096
#define BATCH   4
#define SEQ     2048
#define NROWS   (BATCH*SEQ)
#define QKVN    3072
#define QKVLD   3072

typedef __half f16;

// ---------------- scratch (device globals; no runtime allocation) ----------
__device__ float g_x1[NROWS * D_MODEL];
__device__ float g_x2[NROWS * D_MODEL];

__device__ f16 g_xnh[NROWS * D_MODEL];
__device__ f16 g_qkvh[(size_t)NROWS * QKVN];
__device__ f16 g_hh [NROWS * D_MODEL];
__device__ f16 g_aoh[NROWS * D_MODEL];
__device__ f16 g_ffh[(size_t)NROWS * D_FF];

__device__ f16 g_wqkvh[QKVN*D_MODEL];
__device__ f16 g_woh[D_MODEL*D_MODEL];
__device__ f16 g_l1h[D_FF*D_MODEL];
__device__ f16 g_l2h[D_MODEL*D_FF];

// ---------------- small PTX helpers ----------------------------------------
__device__ __forceinline__ uint32_t smem_u32(const void* p) {
    uint32_t a;
    asm("{ .reg .u64 t; cvta.to.shared.u64 t, %1; cvt.u32.u64 %0, t; }"
        : "=r"(a) : "l"(p));
    return a;
}
__device__ __forceinline__ void cpasync16(uint32_t dst, const void* src) {
    asm volatile("cp.async.cg.shared.global [%0], [%1], 16;"
                 :: "r"(dst), "l"(src));
}
#define CP_COMMIT() asm volatile("cp.async.commit_group;" ::: "memory")
#define CP_WAIT2()  asm volatile("cp.async.wait_group 2;" ::: "memory")
#define CP_WAIT1()  asm volatile("cp.async.wait_group 1;" ::: "memory")
#define CP_WAIT0()  asm volatile("cp.async.wait_group 0;" ::: "memory")

__device__ __forceinline__ void ldm4(uint32_t* r, uint32_t addr) {
    asm volatile("ldmatrix.sync.aligned.m8n8.x4.shared.b16 {%0,%1,%2,%3}, [%4];"
        : "=r"(r[0]), "=r"(r[1]), "=r"(r[2]), "=r"(r[3]) : "r"(addr));
}
__device__ __forceinline__ void ldm4t(uint32_t* r, uint32_t addr) {
    asm volatile("ldmatrix.sync.aligned.m8n8.x4.trans.shared.b16 {%0,%1,%2,%3}, [%4];"
        : "=r"(r[0]), "=r"(r[1]), "=r"(r[2]), "=r"(r[3]) : "r"(addr));
}
__device__ __forceinline__ void mma16816(float* c, const uint32_t* a,
                                         uint32_t b0, uint32_t b1) {
    asm volatile("mma.sync.aligned.m16n8k16.row.col.f32.f16.f16.f32 "
        "{%0,%1,%2,%3}, {%4,%5,%6,%7}, {%8,%9}, {%0,%1,%2,%3};"
        : "+f"(c[0]), "+f"(c[1]), "+f"(c[2]), "+f"(c[3])
        : "r"(a[0]), "r"(a[1]), "r"(a[2]), "r"(a[3]), "r"(b0), "r"(b1));
}
__device__ __forceinline__ uint32_t packh(f16 a, f16 b) {
    return (uint32_t)__half_as_ushort(a) |
           ((uint32_t)__half_as_ushort(b) << 16);
}

// ---------------- weight fp32 -> fp16 conversion ----------------------------
__global__ __launch_bounds__(256) void cvt_kernel(
    const float4* __restrict__ src, ushort4* __restrict__ hi, int n4)
{
    int i = blockIdx.x * 256 + threadIdx.x;
    if (i >= n4) return;
    float4 v = src[i];
    hi[i] = make_ushort4(
        __half_as_ushort(__float2half_rn(v.x)),
        __half_as_ushort(__float2half_rn(v.y)),
        __half_as_ushort(__float2half_rn(v.z)),
        __half_as_ushort(__float2half_rn(v.w)));
}

// ---------------- layernorm (unbiased std) ----------------------------------
__device__ __forceinline__ float block_sum(float v, float* red) {
    __syncthreads();
    #pragma unroll
    for (int o = 16; o; o >>= 1) v += __shfl_xor_sync(0xffffffffu, v, o);
    int tid = threadIdx.x;
    if ((tid & 31) == 0) red[tid >> 5] = v;
    __syncthreads();
    if (tid == 0) {
        float t = 0.f;
        #pragma unroll
        for (int i = 0; i < 8; i++) t += red[i];
        red[0] = t;
    }
    __syncthreads();
    return red[0];
}

template<bool F16OUT>
__global__ __launch_bounds__(256) void ln_kernel(
    const float* __restrict__ x, const float* __restrict__ ga,
    const float* __restrict__ gb, float* __restrict__ out,
    f16* __restrict__ oh)
{
    __shared__ float red[8];
    const int row = blockIdx.x;
    const int tid = threadIdx.x;
    const float4 v = reinterpret_cast<const float4*>(x + (size_t)row * D_MODEL)[tid];

    float s = v.x + v.y + v.z + v.w;
    const float mean = block_sum(s, red) * (1.0f / D_MODEL);

    float4 d = make_float4(v.x - mean, v.y - mean, v.z - mean, v.w - mean);
    float sq = d.x*d.x + d.y*d.y + d.z*d.z + d.w*d.w;
    const float var = block_sum(sq, red) * (1.0f / (D_MODEL - 1));
    const float rstd = rsqrtf(var);

    const float4 a = reinterpret_cast<const float4*>(ga)[tid];
    const float4 b = reinterpret_cast<const float4*>(gb)[tid];
    float4 o;
    o.x = d.x * rstd * a.x + b.x;
    o.y = d.y * rstd * a.y + b.y;
    o.z = d.z * rstd * a.z + b.z;
    o.w = d.w * rstd * a.w + b.w;
    if (F16OUT) {
        const size_t idx = (size_t)row * (D_MODEL/4) + tid;
        reinterpret_cast<ushort4*>(oh)[idx] = make_ushort4(
            __half_as_ushort(__float2half_rn(o.x)),
            __half_as_ushort(__float2half_rn(o.y)),
            __half_as_ushort(__float2half_rn(o.z)),
            __half_as_ushort(__float2half_rn(o.w)));
    } else {
        reinterpret_cast<float4*>(out + (size_t)row * D_MODEL)[tid] = o;
    }
}

// ---------------- mma.sync fp16 single-pass GEMM -----------------------------
// C = A(fp16) @ W(fp16)^T, fp32 accum. BM=BN=128, BK=32,
// 4-stage cp.async pipeline (loads 3 iters ahead), 2 CTAs/SM.
// OMODE: 0 = fp32 out, 1 = fp16 out.
#define NSTG      4
#define ROWB      80
#define TILE_B    (128*ROWB)
#define STAGE_B   (2*TILE_B)          // Ah, Wh
#define GEMM_SMEM (NSTG*STAGE_B)      // 81920 B

template<bool RELU, bool HASB, bool HASR, int OMODE>
__global__ __launch_bounds__(256, 2) void gemm_tc(
    const f16* __restrict__ Ah, const f16* __restrict__ Wh,
    const float* __restrict__ bias, const float* __restrict__ res,
    float* __restrict__ C, f16* __restrict__ Ch,
    int M, int N, int K)
{
    extern __shared__ char smem[];
    const uint32_t sb = smem_u32(smem);
    const int tid  = threadIdx.x;
    const int bm   = blockIdx.y << 7;
    const int bn   = blockIdx.x << 7;
    const int w    = tid >> 5, lane = tid & 31;
    const int mblock = (w & 3) << 5;
    const int nblock = (w >> 2) << 6;

    const uint32_t aRowByte = (uint32_t)(mblock + (lane & 15)) * ROWB
                            + ((lane >> 4) & 1) * 16;
    const uint32_t bRowByte = (uint32_t)(nblock + ((lane >> 4) << 3) + (lane & 7)) * ROWB
                            + ((lane >> 3) & 1) * 16;

    float acc[2][8][4];
    #pragma unroll
    for (int i = 0; i < 2; i++)
        #pragma unroll
        for (int j = 0; j < 8; j++)
            #pragma unroll
            for (int t = 0; t < 4; t++) acc[i][j][t] = 0.f;

    auto load1 = [&](const f16* __restrict__ src, int row0, uint32_t sbase, int kt) {
        #pragma unroll
        for (int i = 0; i < 2; i++) {
            const int ch = tid + (i << 8);
            const int r = ch >> 2, c = ch & 3;
            cpasync16(sbase + (uint32_t)r * ROWB + c * 16,
                      src + (size_t)(row0 + r) * K + (kt << 5) + (c << 3));
        }
    };
    auto load_stage = [&](int kt, int slot) {
        const uint32_t base = sb + slot * STAGE_B;
        load1(Ah, bm, base,          kt);
        load1(Wh, bn, base + TILE_B, kt);
    };

    const int NK = K >> 5;
    load_stage(0, 0); CP_COMMIT();
    load_stage(1, 1); CP_COMMIT();
    load_stage(2, 2); CP_COMMIT();

    for (int kt = 0; kt < NK; ++kt) {
        CP_WAIT2();
        __syncthreads();

        const int nt = kt + 3;
        if (nt < NK) load_stage(nt, nt & 3);
        CP_COMMIT();

        const uint32_t st = sb + (kt & 3) * STAGE_B;
        const uint32_t aHi = st + aRowByte;
        const uint32_t bHi = st + TILE_B + bRowByte;

        #pragma unroll
        for (int ks = 0; ks < 2; ++ks) {
            uint32_t ah[2][4];
            #pragma unroll
            for (int mt = 0; mt < 2; mt++)
                ldm4(ah[mt], aHi + mt*(16*ROWB) + ks*32);
            #pragma unroll
            for (int np = 0; np < 4; np++) {
                uint32_t bh4[4];
                ldm4(bh4, bHi + np*(16*ROWB) + ks*32);
                #pragma unroll
                for (int mt = 0; mt < 2; mt++)
                    #pragma unroll
                    for (int h = 0; h < 2; h++)
                        mma16816(acc[mt][np*2 + h], ah[mt], bh4[h*2], bh4[h*2+1]);
            }
        }
    }

    #pragma unroll
    for (int mt = 0; mt < 2; mt++) {
        #pragma unroll
        for (int nt = 0; nt < 8; nt++) {
            const int r0 = bm + mblock + mt*16 + (lane >> 2);
            const int c0 = bn + nblock + nt*8 + ((lane & 3) << 1);
            float v00 = acc[mt][nt][0], v01 = acc[mt][nt][1];
            float v10 = acc[mt][nt][2], v11 = acc[mt][nt][3];
            if (HASB) {
                const float2 bb = *(const float2*)(bias + c0);
                v00 += bb.x; v01 += bb.y; v10 += bb.x; v11 += bb.y;
            }
            if (RELU) {
                v00 = fmaxf(v00, 0.f); v01 = fmaxf(v01, 0.f);
                v10 = fmaxf(v10, 0.f); v11 = fmaxf(v11, 0.f);
            }
            const size_t o0 = (size_t)r0 * N + c0;
            const size_t o1 = o0 + (size_t)8 * N;
            if (HASR) {
                const float2 r4a = *(const float2*)(res + o0);
                const float2 r4b = *(const float2*)(res + o1);
                v00 += r4a.x; v01 += r4a.y; v10 += r4b.x; v11 += r4b.y;
            }
            if (OMODE == 0) {
                *(float2*)(C + o0) = make_float2(v00, v01);
                *(float2*)(C + o1) = make_float2(v10, v11);
            } else {
                *(uint32_t*)(Ch + o0) = packh(__float2half_rn(v00), __float2half_rn(v01));
                *(uint32_t*)(Ch + o1) = packh(__float2half_rn(v10), __float2half_rn(v11));
            }
        }
    }
}

// ---------------- tensor-core flash attention (fp16 single-pass) -------------
#define AROWB 144
#define ATILE (64*AROWB)              // 9216 B
#define ASTG  (2*ATILE)               // Kh, Vh
#define SM_KV ATILE                   // after Qh
#define SM_MASK (SM_KV + 2*ASTG)      // 46080
#define ATTN_SMEM (SM_MASK + 512)     // 46592 B

__global__ __launch_bounds__(128) void attn_tc(
    const f16* __restrict__ QKVh,
    const int* __restrict__ mask,
    f16* __restrict__ Oh)
{
    extern __shared__ char smem[];
    const uint32_t sb = smem_u32(smem);
    const int tid = threadIdx.x, w = tid >> 5, lane = tid & 31;
    const int q0 = blockIdx.x << 6;
    const int h  = blockIdx.y, b = blockIdx.z;
    const size_t hoff = (size_t)h * DKH;
    const int g = lane >> 2, t4 = lane & 3;

    const f16* Qh_ = QKVh;
    const f16* Kh_ = QKVh + 1024;
    const f16* Vh_ = QKVh + 2048;

    // Q tile (64 x 64 fp16)
    #pragma unroll
    for (int i = 0; i < 4; i++) {
        const int ch = tid + (i << 7);
        const int r = ch >> 3, c = ch & 7;
        cpasync16(sb + (uint32_t)r * AROWB + c * 16,
                  Qh_ + (size_t)(b * SEQ + q0 + r) * QKVLD + hoff + (c << 3));
    }
    auto loadKV = [&](int blk, int slot) {
        const uint32_t base = sb + SM_KV + slot * ASTG;
        const f16* srcs[2] = {Kh_, Vh_};
        #pragma unroll
        for (int tI = 0; tI < 2; tI++) {
            #pragma unroll
            for (int i = 0; i < 4; i++) {
                const int ch = tid + (i << 7);
                const int r = ch >> 3, c = ch & 7;
                cpasync16(base + tI * ATILE + (uint32_t)r * AROWB + c * 16,
                          srcs[tI] + (size_t)(b * SEQ + (blk << 6) + r) * QKVLD
                                   + hoff + (c << 3));
            }
        }
        if (tid < 16)
            cpasync16(sb + SM_MASK + slot * 256 + tid * 16,
                      mask + (size_t)b * SEQ + (blk << 6) + tid * 4);
    };

    loadKV(0, 0);
    CP_COMMIT();

    uint32_t qh[4][4];
    float o[8][4];
    #pragma unroll
    for (int i = 0; i < 8; i++)
        #pragma unroll
        for (int j = 0; j < 4; j++) o[i][j] = 0.f;
    float m0 = -INFINITY, m1 = -INFINITY, l0 = 0.f, l1 = 0.f;

    const uint32_t aoff = (uint32_t)((w * 16 + (lane & 15)) * AROWB)
                        + (((lane >> 4) & 1) << 4);
    const uint32_t boff = (uint32_t)((((lane >> 4) << 3) + (lane & 7)) * AROWB)
                        + (((lane >> 3) & 1) << 4);
    const uint32_t voff = (uint32_t)((lane & 15) * AROWB) + ((lane >> 4) << 4);

    const int NB = SEQ / 64;
    for (int it = 0; it < NB; ++it) {
        if (it + 1 < NB) { loadKV(it + 1, (it + 1) & 1); CP_COMMIT(); CP_WAIT1(); }
        else             { CP_WAIT0(); }
        __syncthreads();

        if (it == 0) {
            #pragma unroll
            for (int ks = 0; ks < 4; ks++)
                ldm4(qh[ks], sb + aoff + ks * 32);
        }

        const uint32_t stg = sb + SM_KV + (it & 1) * ASTG;
        const int* msk = (const int*)(smem + SM_MASK + (it & 1) * 256);

        // ---- S = Q @ K^T ----
        float sa[8][4];
        #pragma unroll
        for (int i = 0; i < 8; i++)
            #pragma unroll
            for (int j = 0; j < 4; j++) sa[i][j] = 0.f;

        #pragma unroll
        for (int ks = 0; ks < 4; ks++) {
            #pragma unroll
            for (int ng = 0; ng < 4; ng++) {
                uint32_t kh4[4];
                ldm4(kh4, stg + boff + ng * (16 * AROWB) + ks * 32);
                mma16816(sa[2*ng],     qh[ks], kh4[0], kh4[1]);
                mma16816(sa[2*ng + 1], qh[ks], kh4[2], kh4[3]);
            }
        }

        // ---- mask + scale ----
        #pragma unroll
        for (int nt = 0; nt < 8; nt++) {
            const int j0 = nt * 8 + (t4 << 1);
            const bool k0m = msk[j0] != 0, k1m = msk[j0 + 1] != 0;
            sa[nt][0] = k0m ? -1e9f : sa[nt][0] * 0.125f;
            sa[nt][1] = k1m ? -1e9f : sa[nt][1] * 0.125f;
            sa[nt][2] = k0m ? -1e9f : sa[nt][2] * 0.125f;
            sa[nt][3] = k1m ? -1e9f : sa[nt][3] * 0.125f;
        }

        // ---- online softmax ----
        float mx0 = -INFINITY, mx1 = -INFINITY;
        #pragma unroll
        for (int nt = 0; nt < 8; nt++) {
            mx0 = fmaxf(mx0, fmaxf(sa[nt][0], sa[nt][1]));
            mx1 = fmaxf(mx1, fmaxf(sa[nt][2], sa[nt][3]));
        }
        mx0 = fmaxf(mx0, __shfl_xor_sync(0xffffffffu, mx0, 1));
        mx0 = fmaxf(mx0, __shfl_xor_sync(0xffffffffu, mx0, 2));
        mx1 = fmaxf(mx1, __shfl_xor_sync(0xffffffffu, mx1, 1));
        mx1 = fmaxf(mx1, __shfl_xor_sync(0xffffffffu, mx1, 2));
        const float nm0 = fmaxf(m0, mx0), nm1 = fmaxf(m1, mx1);
        const float f0 = __expf(m0 - nm0), f1 = __expf(m1 - nm1);

        float s0 = 0.f, s1 = 0.f;
        #pragma unroll
        for (int nt = 0; nt < 8; nt++) {
            sa[nt][0] = __expf(sa[nt][0] - nm0);
            sa[nt][1] = __expf(sa[nt][1] - nm0);
            sa[nt][2] = __expf(sa[nt][2] - nm1);
            sa[nt][3] = __expf(sa[nt][3] - nm1);
            s0 += sa[nt][0] + sa[nt][1];
            s1 += sa[nt][2] + sa[nt][3];
        }
        s0 += __shfl_xor_sync(0xffffffffu, s0, 1);
        s0 += __shfl_xor_sync(0xffffffffu, s0, 2);
        s1 += __shfl_xor_sync(0xffffffffu, s1, 1);
        s1 += __shfl_xor_sync(0xffffffffu, s1, 2);
        m0 = nm0; m1 = nm1;
        l0 = l0 * f0 + s0;
        l1 = l1 * f1 + s1;
        #pragma unroll
        for (int d = 0; d < 8; d++) {
            o[d][0] *= f0; o[d][1] *= f0;
            o[d][2] *= f1; o[d][3] *= f1;
        }

        // ---- repack P (fp16 a-fragments) ----
        uint32_t pah[4][4];
        #pragma unroll
        for (int ks = 0; ks < 4; ks++) {
            #pragma unroll
            for (int half = 0; half < 2; half++) {
                const float* sv = sa[2*ks + half];
                pah[ks][half*2 + 0] = packh(__float2half_rn(sv[0]),
                                            __float2half_rn(sv[1]));
                pah[ks][half*2 + 1] = packh(__float2half_rn(sv[2]),
                                            __float2half_rn(sv[3]));
            }
        }

        // ---- O += P @ V ----
        #pragma unroll
        for (int ks = 0; ks < 4; ks++) {
            #pragma unroll
            for (int dg = 0; dg < 4; dg++) {
                uint32_t vh4[4];
                ldm4t(vh4, stg + ATILE + voff + ks * (16 * AROWB) + dg * 32);
                mma16816(o[2*dg],     pah[ks], vh4[0], vh4[1]);
                mma16816(o[2*dg + 1], pah[ks], vh4[2], vh4[3]);
            }
        }
        __syncthreads();
    }

    // ---- epilogue ----
    const float i0 = 1.f / l0, i1 = 1.f / l1;
    const size_t r0 = (size_t)(b * SEQ + q0 + w * 16 + g) * D_MODEL + hoff;
    const size_t r1 = r0 + (size_t)8 * D_MODEL;
    #pragma unroll
    for (int d = 0; d < 8; d++) {
        const int col = d * 8 + (t4 << 1);
        *(uint32_t*)(Oh + r0 + col) = packh(__float2half_rn(o[d][0] * i0),
                                            __float2half_rn(o[d][1] * i0));
        *(uint32_t*)(Oh + r1 + col) = packh(__float2half_rn(o[d][2] * i1),
                                            __float2half_rn(o[d][3] * i1));
    }
}

// ---------------- launch -----------------------------------------------------
extern "C" void kernel_launch(void* const* d_in, const int* in_sizes, int n_in,
                              void* d_out, int out_size)
{
    const float* x     = (const float*)d_in[0];
    const float* w_q   = (const float*)d_in[1];
    const float* w_k   = (const float*)d_in[2];
    const float* w_v   = (const float*)d_in[3];
    const float* w_o   = (const float*)d_in[4];
    const float* l1_w  = (const float*)d_in[5];
    const float* l1_b  = (const float*)d_in[6];
    const float* l2_w  = (const float*)d_in[7];
    const float* l2_b  = (const float*)d_in[8];
    const float* n1a   = (const float*)d_in[9];
    const float* n1b   = (const float*)d_in[10];
    const float* n2a   = (const float*)d_in[11];
    const float* n2b   = (const float*)d_in[12];
    const float* nfa   = (const float*)d_in[13];
    const float* nfb   = (const float*)d_in[14];
    const int*   mask  = (const int*)d_in[15];
    float* out = (float*)d_out;

    float *x1, *x2;
    f16 *xnh,*qkvh,*hh,*aoh,*ffh;
    f16 *wqkvh,*woh,*l1h,*l2h;
    cudaGetSymbolAddress((void**)&x1, g_x1);
    cudaGetSymbolAddress((void**)&x2, g_x2);
    cudaGetSymbolAddress((void**)&xnh, g_xnh);
    cudaGetSymbolAddress((void**)&qkvh, g_qkvh);
    cudaGetSymbolAddress((void**)&hh,  g_hh);
    cudaGetSymbolAddress((void**)&aoh, g_aoh);
    cudaGetSymbolAddress((void**)&ffh, g_ffh);
    cudaGetSymbolAddress((void**)&wqkvh, g_wqkvh);
    cudaGetSymbolAddress((void**)&woh, g_woh);
    cudaGetSymbolAddress((void**)&l1h, g_l1h);
    cudaGetSymbolAddress((void**)&l2h, g_l2h);

    cudaFuncSetAttribute(gemm_tc<false,false,false,1>,
        cudaFuncAttributeMaxDynamicSharedMemorySize, GEMM_SMEM);
    cudaFuncSetAttribute(gemm_tc<false,false,true,0>,
        cudaFuncAttributeMaxDynamicSharedMemorySize, GEMM_SMEM);
    cudaFuncSetAttribute(gemm_tc<true,true,false,1>,
        cudaFuncAttributeMaxDynamicSharedMemorySize, GEMM_SMEM);
    cudaFuncSetAttribute(gemm_tc<false,true,true,0>,
        cudaFuncAttributeMaxDynamicSharedMemorySize, GEMM_SMEM);
    cudaFuncSetAttribute(attn_tc,
        cudaFuncAttributeMaxDynamicSharedMemorySize, ATTN_SMEM);

    const int nDD4 = D_MODEL*D_MODEL/4, nFD4 = D_FF*D_MODEL/4;
    // fused QKV weights: rows 0..1023 = w_q, 1024..2047 = w_k, 2048..3071 = w_v
    cvt_kernel<<<(nDD4+255)/256, 256>>>((const float4*)w_q,
        (ushort4*)wqkvh,               nDD4);
    cvt_kernel<<<(nDD4+255)/256, 256>>>((const float4*)w_k,
        (ushort4*)(wqkvh + 1024*1024), nDD4);
    cvt_kernel<<<(nDD4+255)/256, 256>>>((const float4*)w_v,
        (ushort4*)(wqkvh + 2048*1024), nDD4);
    cvt_kernel<<<(nDD4+255)/256, 256>>>((const float4*)w_o,  (ushort4*)woh, nDD4);
    cvt_kernel<<<(nFD4+255)/256, 256>>>((const float4*)l1_w, (ushort4*)l1h, nFD4);
    cvt_kernel<<<(nFD4+255)/256, 256>>>((const float4*)l2_w, (ushort4*)l2h, nFD4);

    const dim3 gQKV(QKVN/128,   NROWS/128);
    const dim3 gD  (D_MODEL/128, NROWS/128);
    const dim3 gF  (D_FF/128,    NROWS/128);

    // 1) xn = LN1(x) -> fp16
    ln_kernel<true><<<NROWS, 256>>>(x, n1a, n1b, nullptr, xnh);
    // 2) fused QKV GEMM -> fp16 [rows, 3072]
    gemm_tc<false,false,false,1><<<gQKV, 256, GEMM_SMEM>>>(
        xnh, wqkvh, nullptr, nullptr, nullptr, qkvh, NROWS, QKVN, D_MODEL);
    // 3) attention -> fp16
    attn_tc<<<dim3(SEQ/64, NH, BATCH), 128, ATTN_SMEM>>>(qkvh, mask, aoh);
    // 4) x1 = x + ao @ w_o^T (fp32)
    gemm_tc<false,false,true,0><<<gD, 256, GEMM_SMEM>>>(
        aoh, woh, nullptr, x, x1, nullptr, NROWS, D_MODEL, D_MODEL);
    // 5) h = LN2(x1) -> fp16
    ln_kernel<true><<<NROWS, 256>>>(x1, n2a, n2b, nullptr, hh);
    // 6) ff = relu(h @ l1^T + b1) -> fp16
    gemm_tc<true,true,false,1><<<gF, 256, GEMM_SMEM>>>(
        hh, l1h, l1_b, nullptr, nullptr, ffh, NROWS, D_FF, D_MODEL);
    // 7) x2 = x1 + ff @ l2^T + b2 (fp32)
    gemm_tc<false,true,true,0><<<gD, 256, GEMM_SMEM>>>(
        ffh, l2h, l2_b, x1, x2, nullptr, NROWS, D_MODEL, D_FF);
    // 8) out = LNf(x2)
    ln_kernel<false><<<NROWS, 256>>>(x2, nfa, nfb, out, nullptr);
}